// round 3
// baseline (speedup 1.0000x reference)
#include <cuda_runtime.h>
#include <math_constants.h>

// ---------------------------------------------------------------------------
// CrossAttention: out = softmax((xWq)(ctxWk)^T * scale) (ctxWv) Wo + bo
// B=4, Nq=2048, Dq=512, Nk=1024, Dc=768, H=8, d=64, inner=512
// Round 2: same fp32 FFMA2 design as R1 (prior bench was an infra failure,
// not a kernel failure) with minor load-batching hardening.
// ---------------------------------------------------------------------------

#define B_     4
#define NQ     2048
#define NK     1024
#define DQ     512
#define DC     768
#define HEADS  8
#define DHEAD  64
#define INNER  512            // HEADS*DHEAD
#define MQ_ALL (B_*NQ)        // 8192
#define MK_ALL (B_*NK)        // 4096
#define SCALE_ 0.125f         // 64^-0.5

// Scratch (allocation-free rule: __device__ globals)
__device__ float g_q [MQ_ALL * INNER];   // 16 MB
__device__ float g_k [MK_ALL * INNER];   //  8 MB
__device__ float g_v [MK_ALL * INNER];   //  8 MB
__device__ float g_ao[MQ_ALL * INNER];   // 16 MB

// ---------------------------------------------------------------------------
// Packed fp32x2 FMA (sm_100+): 2 FMAs per instruction, only reachable via PTX.
// ---------------------------------------------------------------------------
__device__ __forceinline__ float2 ffma2(float2 a, float2 b, float2 c) {
    float2 d;
    asm("fma.rn.f32x2 %0, %1, %2, %3;"
        : "=l"(*reinterpret_cast<unsigned long long*>(&d))
        : "l"(*reinterpret_cast<const unsigned long long*>(&a)),
          "l"(*reinterpret_cast<const unsigned long long*>(&b)),
          "l"(*reinterpret_cast<const unsigned long long*>(&c)));
    return d;
}
__device__ __forceinline__ float2 bcast2(float a) { return make_float2(a, a); }

// ---------------------------------------------------------------------------
// SGEMM: C[M,N] = A[M,K] @ W[K,N] (+ bias). 128x128 block tile, BK=16,
// 256 threads, 8x8 micro-tile per thread, FFMA2 inner loop.
// Requires M%128==0, N%128==0, K%16==0 (true for all 4 call sites).
// ---------------------------------------------------------------------------
__global__ void __launch_bounds__(256)
sgemm128(const float* __restrict__ A, const float* __restrict__ W,
         const float* __restrict__ bias, float* __restrict__ C,
         int M, int N, int K)
{
    __shared__ float As[16][132];   // transposed A tile: As[k][m]
    __shared__ float Ws[16][132];   // W tile: Ws[k][n]

    const int tid = threadIdx.x;
    const int tx  = tid & 15;
    const int ty  = tid >> 4;
    const int m0  = blockIdx.y * 128;
    const int n0  = blockIdx.x * 128;

    float2 acc[8][4];
    #pragma unroll
    for (int r = 0; r < 8; ++r)
        #pragma unroll
        for (int c = 0; c < 4; ++c) acc[r][c] = make_float2(0.f, 0.f);

    for (int k0 = 0; k0 < K; k0 += 16) {
        // load A tile (128 rows x 16 k) -> transposed
        #pragma unroll
        for (int li = 0; li < 2; ++li) {
            int fi  = tid + li * 256;        // 0..511 float4 slots
            int row = fi >> 2;               // 0..127
            int c4  = (fi & 3) << 2;         // 0,4,8,12
            float4 v = *(const float4*)&A[(size_t)(m0 + row) * K + k0 + c4];
            As[c4 + 0][row] = v.x;
            As[c4 + 1][row] = v.y;
            As[c4 + 2][row] = v.z;
            As[c4 + 3][row] = v.w;
        }
        // load W tile (16 k x 128 n)
        #pragma unroll
        for (int li = 0; li < 2; ++li) {
            int fi  = tid + li * 256;
            int row = fi >> 5;               // 0..15
            int c4  = (fi & 31) << 2;        // 0..124
            *(float4*)&Ws[row][c4] =
                *(const float4*)&W[(size_t)(k0 + row) * N + n0 + c4];
        }
        __syncthreads();

        #pragma unroll
        for (int kk = 0; kk < 16; ++kk) {
            float4 a0 = *(const float4*)&As[kk][ty * 8];
            float4 a1 = *(const float4*)&As[kk][ty * 8 + 4];
            float4 b0 = *(const float4*)&Ws[kk][tx * 8];
            float4 b1 = *(const float4*)&Ws[kk][tx * 8 + 4];
            float  av[8] = {a0.x, a0.y, a0.z, a0.w, a1.x, a1.y, a1.z, a1.w};
            float2 bv[4] = {make_float2(b0.x, b0.y), make_float2(b0.z, b0.w),
                            make_float2(b1.x, b1.y), make_float2(b1.z, b1.w)};
            #pragma unroll
            for (int r = 0; r < 8; ++r) {
                float2 ar = bcast2(av[r]);
                #pragma unroll
                for (int c = 0; c < 4; ++c)
                    acc[r][c] = ffma2(ar, bv[c], acc[r][c]);
            }
        }
        __syncthreads();
    }

    #pragma unroll
    for (int r = 0; r < 8; ++r) {
        int row = m0 + ty * 8 + r;
        int col = n0 + tx * 8;
        float4 o0 = make_float4(acc[r][0].x, acc[r][0].y, acc[r][1].x, acc[r][1].y);
        float4 o1 = make_float4(acc[r][2].x, acc[r][2].y, acc[r][3].x, acc[r][3].y);
        if (bias) {
            o0.x += bias[col + 0]; o0.y += bias[col + 1];
            o0.z += bias[col + 2]; o0.w += bias[col + 3];
            o1.x += bias[col + 4]; o1.y += bias[col + 5];
            o1.z += bias[col + 6]; o1.w += bias[col + 7];
        }
        *(float4*)&C[(size_t)row * N + col]     = o0;
        *(float4*)&C[(size_t)row * N + col + 4] = o1;
    }
}

// ---------------------------------------------------------------------------
// Flash attention (fp32, online softmax). One block = one (b,h) x 64-row Q tile.
// blockDim (16,16). KV tiled by 64. Q pre-scaled by SCALE_ at load.
// Writes head-merged result to g_ao[row][h*64 + c].
// ---------------------------------------------------------------------------
#define LD 68                       // 64 + 4 pad (keeps 16B alignment)
#define ATTN_SMEM_BYTES (4 * 64 * LD * 4)   // Qt, Kt, Vs, Pt = 69632 B

__global__ void __launch_bounds__(256)
attn_kernel(const float* __restrict__ q, const float* __restrict__ k,
            const float* __restrict__ v, float* __restrict__ o)
{
    extern __shared__ float sm[];
    float* Qt = sm;                 // Qt[d][i]  (64 x LD)
    float* Kt = Qt + 64 * LD;       // Kt[d][j]
    float* Vs = Kt + 64 * LD;       // Vs[j][c]
    float* Pt = Vs + 64 * LD;       // Pt[j][i]

    const int tx  = threadIdx.x;    // 0..15
    const int ty  = threadIdx.y;    // 0..15
    const int tid = ty * 16 + tx;
    const int i0  = ty * 4;         // q-row group
    const int j0  = tx * 4;         // kv-col group / O d-col group

    const int bh = blockIdx.y;      // 0..31
    const int b  = bh >> 3;
    const int h  = bh & 7;
    const int qbase = b * NQ + blockIdx.x * 64;
    const int kbase = b * NK;
    const int hcol  = h * DHEAD;

    // load Q tile (scaled) transposed; 4 iterations, batched LDGs
    #pragma unroll 4
    for (int idx = tid; idx < 64 * 16; idx += 256) {
        int i  = idx >> 4;
        int d4 = (idx & 15) << 2;
        float4 qv = *(const float4*)&q[(size_t)(qbase + i) * INNER + hcol + d4];
        Qt[(d4 + 0) * LD + i] = qv.x * SCALE_;
        Qt[(d4 + 1) * LD + i] = qv.y * SCALE_;
        Qt[(d4 + 2) * LD + i] = qv.z * SCALE_;
        Qt[(d4 + 3) * LD + i] = qv.w * SCALE_;
    }

    float  mrow[4], lrow[4];
    float2 oacc[4][2];
    #pragma unroll
    for (int r = 0; r < 4; ++r) {
        mrow[r] = -CUDART_INF_F;
        lrow[r] = 0.f;
        oacc[r][0] = make_float2(0.f, 0.f);
        oacc[r][1] = make_float2(0.f, 0.f);
    }

    for (int jt = 0; jt < NK / 64; ++jt) {
        __syncthreads();   // protects Kt/Vs reuse and Pt from previous iter
        const int krow0 = kbase + jt * 64;
        #pragma unroll 4
        for (int idx = tid; idx < 64 * 16; idx += 256) {
            int j  = idx >> 4;
            int d4 = (idx & 15) << 2;
            float4 kv = *(const float4*)&k[(size_t)(krow0 + j) * INNER + hcol + d4];
            Kt[(d4 + 0) * LD + j] = kv.x;
            Kt[(d4 + 1) * LD + j] = kv.y;
            Kt[(d4 + 2) * LD + j] = kv.z;
            Kt[(d4 + 3) * LD + j] = kv.w;
            *(float4*)&Vs[j * LD + d4] =
                *(const float4*)&v[(size_t)(krow0 + j) * INNER + hcol + d4];
        }
        __syncthreads();

        // S = Q @ K^T  (already scaled)
        float2 sacc[4][2];
        #pragma unroll
        for (int r = 0; r < 4; ++r) {
            sacc[r][0] = make_float2(0.f, 0.f);
            sacc[r][1] = make_float2(0.f, 0.f);
        }
        #pragma unroll 8
        for (int d = 0; d < 64; ++d) {
            float4 aq = *(const float4*)&Qt[d * LD + i0];
            float4 bk = *(const float4*)&Kt[d * LD + j0];
            float2 b01 = make_float2(bk.x, bk.y);
            float2 b23 = make_float2(bk.z, bk.w);
            sacc[0][0] = ffma2(bcast2(aq.x), b01, sacc[0][0]);
            sacc[0][1] = ffma2(bcast2(aq.x), b23, sacc[0][1]);
            sacc[1][0] = ffma2(bcast2(aq.y), b01, sacc[1][0]);
            sacc[1][1] = ffma2(bcast2(aq.y), b23, sacc[1][1]);
            sacc[2][0] = ffma2(bcast2(aq.z), b01, sacc[2][0]);
            sacc[2][1] = ffma2(bcast2(aq.z), b23, sacc[2][1]);
            sacc[3][0] = ffma2(bcast2(aq.w), b01, sacc[3][0]);
            sacc[3][1] = ffma2(bcast2(aq.w), b23, sacc[3][1]);
        }

        // online softmax update per q-row
        #pragma unroll
        for (int r = 0; r < 4; ++r) {
            float rmax = fmaxf(fmaxf(sacc[r][0].x, sacc[r][0].y),
                               fmaxf(sacc[r][1].x, sacc[r][1].y));
            #pragma unroll
            for (int off = 1; off < 16; off <<= 1)
                rmax = fmaxf(rmax, __shfl_xor_sync(0xffffffffu, rmax, off));
            float nm    = fmaxf(mrow[r], rmax);
            float alpha = __expf(mrow[r] - nm);
            mrow[r] = nm;

            sacc[r][0].x = __expf(sacc[r][0].x - nm);
            sacc[r][0].y = __expf(sacc[r][0].y - nm);
            sacc[r][1].x = __expf(sacc[r][1].x - nm);
            sacc[r][1].y = __expf(sacc[r][1].y - nm);
            float rsum = sacc[r][0].x + sacc[r][0].y + sacc[r][1].x + sacc[r][1].y;
            #pragma unroll
            for (int off = 1; off < 16; off <<= 1)
                rsum += __shfl_xor_sync(0xffffffffu, rsum, off);

            lrow[r] = lrow[r] * alpha + rsum;
            oacc[r][0].x *= alpha; oacc[r][0].y *= alpha;
            oacc[r][1].x *= alpha; oacc[r][1].y *= alpha;
        }

        // stage P transposed: Pt[j][i]
        #pragma unroll
        for (int c = 0; c < 4; ++c) {
            float p0 = (c < 2) ? ((c == 0) ? sacc[0][0].x : sacc[0][0].y)
                               : ((c == 2) ? sacc[0][1].x : sacc[0][1].y);
            float p1 = (c < 2) ? ((c == 0) ? sacc[1][0].x : sacc[1][0].y)
                               : ((c == 2) ? sacc[1][1].x : sacc[1][1].y);
            float p2 = (c < 2) ? ((c == 0) ? sacc[2][0].x : sacc[2][0].y)
                               : ((c == 2) ? sacc[2][1].x : sacc[2][1].y);
            float p3 = (c < 2) ? ((c == 0) ? sacc[3][0].x : sacc[3][0].y)
                               : ((c == 2) ? sacc[3][1].x : sacc[3][1].y);
            *(float4*)&Pt[(j0 + c) * LD + i0] = make_float4(p0, p1, p2, p3);
        }
        __syncthreads();

        // O += P @ V
        #pragma unroll 8
        for (int j = 0; j < 64; ++j) {
            float4 pv = *(const float4*)&Pt[j * LD + i0];
            float4 vv = *(const float4*)&Vs[j * LD + j0];
            float2 v01 = make_float2(vv.x, vv.y);
            float2 v23 = make_float2(vv.z, vv.w);
            oacc[0][0] = ffma2(bcast2(pv.x), v01, oacc[0][0]);
            oacc[0][1] = ffma2(bcast2(pv.x), v23, oacc[0][1]);
            oacc[1][0] = ffma2(bcast2(pv.y), v01, oacc[1][0]);
            oacc[1][1] = ffma2(bcast2(pv.y), v23, oacc[1][1]);
            oacc[2][0] = ffma2(bcast2(pv.z), v01, oacc[2][0]);
            oacc[2][1] = ffma2(bcast2(pv.z), v23, oacc[2][1]);
            oacc[3][0] = ffma2(bcast2(pv.w), v01, oacc[3][0]);
            oacc[3][1] = ffma2(bcast2(pv.w), v23, oacc[3][1]);
        }
    }

    // normalize + write head-merged output
    #pragma unroll
    for (int r = 0; r < 4; ++r) {
        float inv = 1.0f / lrow[r];
        size_t base = (size_t)(qbase + i0 + r) * INNER + hcol + j0;
        *(float4*)&o[base] = make_float4(oacc[r][0].x * inv, oacc[r][0].y * inv,
                                         oacc[r][1].x * inv, oacc[r][1].y * inv);
    }
}

// ---------------------------------------------------------------------------
// Launch
// ---------------------------------------------------------------------------
extern "C" void kernel_launch(void* const* d_in, const int* in_sizes, int n_in,
                              void* d_out, int out_size)
{
    (void)in_sizes; (void)n_in; (void)out_size;
    const float* x   = (const float*)d_in[0];
    const float* ctx = (const float*)d_in[1];
    const float* Wq  = (const float*)d_in[2];
    const float* Wk  = (const float*)d_in[3];
    const float* Wv  = (const float*)d_in[4];
    const float* Wo  = (const float*)d_in[5];
    const float* bo  = (const float*)d_in[6];
    float* out = (float*)d_out;

    float *q, *k, *v, *ao;
    cudaGetSymbolAddress((void**)&q,  g_q);
    cudaGetSymbolAddress((void**)&k,  g_k);
    cudaGetSymbolAddress((void**)&v,  g_v);
    cudaGetSymbolAddress((void**)&ao, g_ao);

    (void)cudaFuncSetAttribute(attn_kernel,
                               cudaFuncAttributeMaxDynamicSharedMemorySize,
                               ATTN_SMEM_BYTES);

    // projections
    sgemm128<<<dim3(INNER / 128, MQ_ALL / 128), 256>>>(x,   Wq, nullptr, q, MQ_ALL, INNER, DQ);
    sgemm128<<<dim3(INNER / 128, MK_ALL / 128), 256>>>(ctx, Wk, nullptr, k, MK_ALL, INNER, DC);
    sgemm128<<<dim3(INNER / 128, MK_ALL / 128), 256>>>(ctx, Wv, nullptr, v, MK_ALL, INNER, DC);

    // attention (grid: 32 q-tiles x 32 (b,h) pairs)
    attn_kernel<<<dim3(NQ / 64, B_ * HEADS), dim3(16, 16), ATTN_SMEM_BYTES>>>(q, k, v, ao);

    // output projection + bias -> d_out
    sgemm128<<<dim3(DQ / 128, MQ_ALL / 128), 256>>>(ao, Wo, bo, out, MQ_ALL, DQ, INNER);
}

// round 4
// speedup vs baseline: 1.1004x; 1.1004x over previous
#include <cuda_runtime.h>
#include <math_constants.h>

// ---------------------------------------------------------------------------
// CrossAttention: out = softmax((xWq)(ctxWk)^T * scale) (ctxWv) Wo + bo
// B=4, Nq=2048, Dq=512, Nk=1024, Dc=768, H=8, d=64, inner=512
// Round 3: attn 128x128 tile / 8x8 micro (fix L1=90% crossbar bound),
// sgemm double-buffered smem with 1 sync/iter. All fp32 FFMA2.
// ---------------------------------------------------------------------------

#define B_     4
#define NQ     2048
#define NK     1024
#define DQ     512
#define DC     768
#define HEADS  8
#define DHEAD  64
#define INNER  512
#define MQ_ALL (B_*NQ)        // 8192
#define MK_ALL (B_*NK)        // 4096
#define SCALE_ 0.125f

__device__ float g_q [MQ_ALL * INNER];
__device__ float g_k [MK_ALL * INNER];
__device__ float g_v [MK_ALL * INNER];
__device__ float g_ao[MQ_ALL * INNER];

__device__ __forceinline__ float2 ffma2(float2 a, float2 b, float2 c) {
    float2 d;
    asm("fma.rn.f32x2 %0, %1, %2, %3;"
        : "=l"(*reinterpret_cast<unsigned long long*>(&d))
        : "l"(*reinterpret_cast<const unsigned long long*>(&a)),
          "l"(*reinterpret_cast<const unsigned long long*>(&b)),
          "l"(*reinterpret_cast<const unsigned long long*>(&c)));
    return d;
}
__device__ __forceinline__ float2 bcast2(float a) { return make_float2(a, a); }

// ---------------------------------------------------------------------------
// SGEMM v2: 128x128 tile, BK=16, 256 threads, 8x8 micro, double-buffered smem,
// one __syncthreads per k-tile. Column split tx*4 / 64+tx*4 (conflict-free).
// ---------------------------------------------------------------------------
__global__ void __launch_bounds__(256)
sgemm128(const float* __restrict__ A, const float* __restrict__ W,
         const float* __restrict__ bias, float* __restrict__ C,
         int M, int N, int K)
{
    __shared__ float As[2][16][132];
    __shared__ float Ws[2][16][132];

    const int tid = threadIdx.x;
    const int tx  = tid & 15;
    const int ty  = tid >> 4;
    const int m0  = blockIdx.y * 128;
    const int n0  = blockIdx.x * 128;

    // load-slot geometry
    const int a_row = (tid * 2) >> 3;          // reuse below via fi math
    (void)a_row;

    float2 acc[8][4];
    #pragma unroll
    for (int r = 0; r < 8; ++r)
        #pragma unroll
        for (int c = 0; c < 4; ++c) acc[r][c] = make_float2(0.f, 0.f);

    const int nk = K >> 4;

    // --- load tile 0 directly into smem buffer 0 ---
    #pragma unroll
    for (int li = 0; li < 2; ++li) {
        int fi  = tid + li * 256;
        int row = fi >> 2;
        int c4  = (fi & 3) << 2;
        float4 v = *(const float4*)&A[(size_t)(m0 + row) * K + c4];
        As[0][c4 + 0][row] = v.x;
        As[0][c4 + 1][row] = v.y;
        As[0][c4 + 2][row] = v.z;
        As[0][c4 + 3][row] = v.w;
    }
    #pragma unroll
    for (int li = 0; li < 2; ++li) {
        int fi  = tid + li * 256;
        int row = fi >> 5;
        int c4  = (fi & 31) << 2;
        *(float4*)&Ws[0][row][c4] = *(const float4*)&W[(size_t)row * N + n0 + c4];
    }
    __syncthreads();

    for (int t = 0; t < nk; ++t) {
        const int cur = t & 1;
        const int nxt = cur ^ 1;

        float4 pa[2], pw[2];
        const bool more = (t + 1 < nk);
        if (more) {
            const int k0n = (t + 1) << 4;
            #pragma unroll
            for (int li = 0; li < 2; ++li) {
                int fi  = tid + li * 256;
                int row = fi >> 2;
                int c4  = (fi & 3) << 2;
                pa[li] = *(const float4*)&A[(size_t)(m0 + row) * K + k0n + c4];
            }
            #pragma unroll
            for (int li = 0; li < 2; ++li) {
                int fi  = tid + li * 256;
                int row = fi >> 5;
                int c4  = (fi & 31) << 2;
                pw[li] = *(const float4*)&W[(size_t)(k0n + row) * N + n0 + c4];
            }
        }

        #pragma unroll
        for (int kk = 0; kk < 16; ++kk) {
            float4 a0 = *(const float4*)&As[cur][kk][ty * 8];
            float4 a1 = *(const float4*)&As[cur][kk][ty * 8 + 4];
            float4 b0 = *(const float4*)&Ws[cur][kk][tx * 4];
            float4 b1 = *(const float4*)&Ws[cur][kk][64 + tx * 4];
            float  av[8] = {a0.x, a0.y, a0.z, a0.w, a1.x, a1.y, a1.z, a1.w};
            float2 bv[4] = {make_float2(b0.x, b0.y), make_float2(b0.z, b0.w),
                            make_float2(b1.x, b1.y), make_float2(b1.z, b1.w)};
            #pragma unroll
            for (int r = 0; r < 8; ++r) {
                float2 ar = bcast2(av[r]);
                #pragma unroll
                for (int c = 0; c < 4; ++c)
                    acc[r][c] = ffma2(ar, bv[c], acc[r][c]);
            }
        }

        if (more) {
            #pragma unroll
            for (int li = 0; li < 2; ++li) {
                int fi  = tid + li * 256;
                int row = fi >> 2;
                int c4  = (fi & 3) << 2;
                As[nxt][c4 + 0][row] = pa[li].x;
                As[nxt][c4 + 1][row] = pa[li].y;
                As[nxt][c4 + 2][row] = pa[li].z;
                As[nxt][c4 + 3][row] = pa[li].w;
            }
            #pragma unroll
            for (int li = 0; li < 2; ++li) {
                int fi  = tid + li * 256;
                int row = fi >> 5;
                int c4  = (fi & 31) << 2;
                *(float4*)&Ws[nxt][row][c4] = pw[li];
            }
            __syncthreads();
        }
    }

    const int col0 = n0 + tx * 4;
    const int col1 = n0 + 64 + tx * 4;
    #pragma unroll
    for (int r = 0; r < 8; ++r) {
        int row = m0 + ty * 8 + r;
        float4 o0 = make_float4(acc[r][0].x, acc[r][0].y, acc[r][1].x, acc[r][1].y);
        float4 o1 = make_float4(acc[r][2].x, acc[r][2].y, acc[r][3].x, acc[r][3].y);
        if (bias) {
            o0.x += bias[col0 + 0]; o0.y += bias[col0 + 1];
            o0.z += bias[col0 + 2]; o0.w += bias[col0 + 3];
            o1.x += bias[col1 + 0]; o1.y += bias[col1 + 1];
            o1.z += bias[col1 + 2]; o1.w += bias[col1 + 3];
        }
        *(float4*)&C[(size_t)row * N + col0] = o0;
        *(float4*)&C[(size_t)row * N + col1] = o1;
    }
}

// ---------------------------------------------------------------------------
// Flash attention v2: 128 q-rows x 128 kv-cols per CTA, 256 threads,
// 8x8 micro-tile (rows ty*4 & 64+ty*4, cols tx*4 & 64+tx*4).
// ---------------------------------------------------------------------------
#define LDP  132                 // leading dim for Qt/Kt/Pt (128+4)
#define LDVV 68                  // leading dim for Vs (64+4)
#define ATTN_SMEM_BYTES ((64*LDP + 64*LDP + 128*LDVV + 128*LDP) * 4)  // 169984

#define SEL(r, lc) (((lc) & 1) ? sacc[r][(lc) >> 1].y : sacc[r][(lc) >> 1].x)

__global__ void __launch_bounds__(256, 1)
attn_kernel(const float* __restrict__ q, const float* __restrict__ k,
            const float* __restrict__ v, float* __restrict__ o)
{
    extern __shared__ float sm[];
    float* Qt = sm;                  // [64][LDP]  (d, i)
    float* Kt = Qt + 64 * LDP;       // [64][LDP]  (d, j)
    float* Vs = Kt + 64 * LDP;       // [128][LDVV] (j, c)
    float* Pt = Vs + 128 * LDVV;     // [128][LDP]  (j, i)

    const int tid = threadIdx.x;
    const int tx  = tid & 15;
    const int ty  = tid >> 4;
    const int rA  = ty * 4;          // S/O row groups
    const int rB  = 64 + ty * 4;
    const int cA  = tx * 4;          // S col groups (cA also O cols)
    const int cB  = 64 + tx * 4;

    const int bh = blockIdx.y;
    const int b  = bh >> 3;
    const int h  = bh & 7;
    const int qbase = b * NQ + blockIdx.x * 128;
    const int kbase = b * NK;
    const int hcol  = h * DHEAD;

    // Q load (scaled, transposed): 128 rows x 16 float4
    #pragma unroll
    for (int it = 0; it < 8; ++it) {
        int idx = tid + it * 256;
        int i   = idx >> 4;
        int d4  = (idx & 15) << 2;
        float4 qv = *(const float4*)&q[(size_t)(qbase + i) * INNER + hcol + d4];
        Qt[(d4 + 0) * LDP + i] = qv.x * SCALE_;
        Qt[(d4 + 1) * LDP + i] = qv.y * SCALE_;
        Qt[(d4 + 2) * LDP + i] = qv.z * SCALE_;
        Qt[(d4 + 3) * LDP + i] = qv.w * SCALE_;
    }

    float  mrow[8], lrow[8];
    float2 oacc[8][2];
    #pragma unroll
    for (int r = 0; r < 8; ++r) {
        mrow[r] = -CUDART_INF_F;
        lrow[r] = 0.f;
        oacc[r][0] = make_float2(0.f, 0.f);
        oacc[r][1] = make_float2(0.f, 0.f);
    }

    for (int jt = 0; jt < NK / 128; ++jt) {
        __syncthreads();
        const int krow0 = kbase + jt * 128;
        #pragma unroll
        for (int it = 0; it < 8; ++it) {
            int idx = tid + it * 256;
            int j   = idx >> 4;
            int d4  = (idx & 15) << 2;
            float4 kv = *(const float4*)&k[(size_t)(krow0 + j) * INNER + hcol + d4];
            Kt[(d4 + 0) * LDP + j] = kv.x;
            Kt[(d4 + 1) * LDP + j] = kv.y;
            Kt[(d4 + 2) * LDP + j] = kv.z;
            Kt[(d4 + 3) * LDP + j] = kv.w;
            *(float4*)&Vs[j * LDVV + d4] =
                *(const float4*)&v[(size_t)(krow0 + j) * INNER + hcol + d4];
        }
        __syncthreads();

        // ---- S = Q K^T (scaled) : 8x8 per thread ----
        float2 sacc[8][4];
        #pragma unroll
        for (int r = 0; r < 8; ++r)
            #pragma unroll
            for (int c = 0; c < 4; ++c) sacc[r][c] = make_float2(0.f, 0.f);

        #pragma unroll 4
        for (int d = 0; d < 64; ++d) {
            float4 qa = *(const float4*)&Qt[d * LDP + rA];
            float4 qb = *(const float4*)&Qt[d * LDP + rB];
            float4 ka = *(const float4*)&Kt[d * LDP + cA];
            float4 kb = *(const float4*)&Kt[d * LDP + cB];
            float  av[8] = {qa.x, qa.y, qa.z, qa.w, qb.x, qb.y, qb.z, qb.w};
            float2 bv[4] = {make_float2(ka.x, ka.y), make_float2(ka.z, ka.w),
                            make_float2(kb.x, kb.y), make_float2(kb.z, kb.w)};
            #pragma unroll
            for (int r = 0; r < 8; ++r) {
                float2 ar = bcast2(av[r]);
                #pragma unroll
                for (int c = 0; c < 4; ++c)
                    sacc[r][c] = ffma2(ar, bv[c], sacc[r][c]);
            }
        }

        // ---- online softmax (reduce across the 16 tx lanes) ----
        #pragma unroll
        for (int r = 0; r < 8; ++r) {
            float rmax = fmaxf(fmaxf(fmaxf(sacc[r][0].x, sacc[r][0].y),
                                     fmaxf(sacc[r][1].x, sacc[r][1].y)),
                               fmaxf(fmaxf(sacc[r][2].x, sacc[r][2].y),
                                     fmaxf(sacc[r][3].x, sacc[r][3].y)));
            #pragma unroll
            for (int off = 1; off < 16; off <<= 1)
                rmax = fmaxf(rmax, __shfl_xor_sync(0xffffffffu, rmax, off));
            float nm    = fmaxf(mrow[r], rmax);
            float alpha = __expf(mrow[r] - nm);
            mrow[r] = nm;

            float rsum = 0.f;
            #pragma unroll
            for (int c = 0; c < 4; ++c) {
                sacc[r][c].x = __expf(sacc[r][c].x - nm);
                sacc[r][c].y = __expf(sacc[r][c].y - nm);
                rsum += sacc[r][c].x + sacc[r][c].y;
            }
            #pragma unroll
            for (int off = 1; off < 16; off <<= 1)
                rsum += __shfl_xor_sync(0xffffffffu, rsum, off);

            lrow[r] = lrow[r] * alpha + rsum;
            oacc[r][0].x *= alpha; oacc[r][0].y *= alpha;
            oacc[r][1].x *= alpha; oacc[r][1].y *= alpha;
        }

        // ---- stage P transposed: Pt[j][i] ----
        #pragma unroll
        for (int lc = 0; lc < 8; ++lc) {
            int pc = (lc < 4) ? (cA + lc) : (cB + lc - 4);
            float4 t0 = make_float4(SEL(0, lc), SEL(1, lc), SEL(2, lc), SEL(3, lc));
            float4 t1 = make_float4(SEL(4, lc), SEL(5, lc), SEL(6, lc), SEL(7, lc));
            *(float4*)&Pt[pc * LDP + rA] = t0;
            *(float4*)&Pt[pc * LDP + rB] = t1;
        }
        __syncthreads();

        // ---- O += P V : rows (rA,rB), cols cA..cA+3 ----
        #pragma unroll 4
        for (int j = 0; j < 128; ++j) {
            float4 p0 = *(const float4*)&Pt[j * LDP + rA];
            float4 p1 = *(const float4*)&Pt[j * LDP + rB];
            float4 vv = *(const float4*)&Vs[j * LDVV + cA];
            float2 v01 = make_float2(vv.x, vv.y);
            float2 v23 = make_float2(vv.z, vv.w);
            float  pr[8] = {p0.x, p0.y, p0.z, p0.w, p1.x, p1.y, p1.z, p1.w};
            #pragma unroll
            for (int r = 0; r < 8; ++r) {
                float2 p2 = bcast2(pr[r]);
                oacc[r][0] = ffma2(p2, v01, oacc[r][0]);
                oacc[r][1] = ffma2(p2, v23, oacc[r][1]);
            }
        }
    }

    // ---- normalize + write (head-merged layout) ----
    #pragma unroll
    for (int r = 0; r < 8; ++r) {
        float inv = 1.0f / lrow[r];
        int   row = qbase + ((r < 4) ? (rA + r) : (rB + r - 4));
        *(float4*)&o[(size_t)row * INNER + hcol + cA] =
            make_float4(oacc[r][0].x * inv, oacc[r][0].y * inv,
                        oacc[r][1].x * inv, oacc[r][1].y * inv);
    }
}

// ---------------------------------------------------------------------------
// Launch
// ---------------------------------------------------------------------------
extern "C" void kernel_launch(void* const* d_in, const int* in_sizes, int n_in,
                              void* d_out, int out_size)
{
    (void)in_sizes; (void)n_in; (void)out_size;
    const float* x   = (const float*)d_in[0];
    const float* ctx = (const float*)d_in[1];
    const float* Wq  = (const float*)d_in[2];
    const float* Wk  = (const float*)d_in[3];
    const float* Wv  = (const float*)d_in[4];
    const float* Wo  = (const float*)d_in[5];
    const float* bo  = (const float*)d_in[6];
    float* out = (float*)d_out;

    float *q, *k, *v, *ao;
    cudaGetSymbolAddress((void**)&q,  g_q);
    cudaGetSymbolAddress((void**)&k,  g_k);
    cudaGetSymbolAddress((void**)&v,  g_v);
    cudaGetSymbolAddress((void**)&ao, g_ao);

    (void)cudaFuncSetAttribute(attn_kernel,
                               cudaFuncAttributeMaxDynamicSharedMemorySize,
                               ATTN_SMEM_BYTES);

    sgemm128<<<dim3(INNER / 128, MQ_ALL / 128), 256>>>(x,   Wq, nullptr, q, MQ_ALL, INNER, DQ);
    sgemm128<<<dim3(INNER / 128, MK_ALL / 128), 256>>>(ctx, Wk, nullptr, k, MK_ALL, INNER, DC);
    sgemm128<<<dim3(INNER / 128, MK_ALL / 128), 256>>>(ctx, Wv, nullptr, v, MK_ALL, INNER, DC);

    attn_kernel<<<dim3(NQ / 128, B_ * HEADS), 256, ATTN_SMEM_BYTES>>>(q, k, v, ao);

    sgemm128<<<dim3(DQ / 128, MQ_ALL / 128), 256>>>(ao, Wo, bo, out, MQ_ALL, DQ, INNER);
}

// round 6
// speedup vs baseline: 1.3762x; 1.2506x over previous
#include <cuda_runtime.h>
#include <cuda_bf16.h>
#include <math_constants.h>
#include <cstdint>

// ---------------------------------------------------------------------------
// CrossAttention: out = softmax((xWq)(ctxWk)^T * scale) (ctxWv) Wo + bo
// B=4, Nq=2048, Dq=512, Nk=1024, Dc=768, H=8, d=64, inner=512
// Round 5: toolchain targets sm_103 (no 'a') => tcgen05 PTX is unavailable.
// Projections use mma.sync bf16 (split hi/lo, 3-MMA) via ldmatrix fragments.
// Attention remains the fp32 FFMA2 flash kernel from R3.
// ---------------------------------------------------------------------------

#define B_     4
#define NQ     2048
#define NK     1024
#define DQ     512
#define DC     768
#define HEADS  8
#define DHEAD  64
#define INNER  512
#define MQ_ALL (B_*NQ)        // 8192
#define MK_ALL (B_*NK)        // 4096
#define SCALE_ 0.125f

// Scratch (__device__ globals; no allocations allowed)
__device__ float g_q [MQ_ALL * INNER];
__device__ float g_k [MK_ALL * INNER];
__device__ float g_v [MK_ALL * INNER];
__device__ float g_ao[MQ_ALL * INNER];

// Transposed+split weights, layout [N][K] bf16, K contiguous.
#define OFF_WQ 0
#define OFF_WK (512*512)
#define OFF_WV (OFF_WK + 512*768)
#define OFF_WO (OFF_WV + 512*768)
#define WT_TOTAL (OFF_WO + 512*512)
__device__ __nv_bfloat16 g_wthi[WT_TOTAL];
__device__ __nv_bfloat16 g_wtlo[WT_TOTAL];

// ---------------------------------------------------------------------------
// helpers
// ---------------------------------------------------------------------------
__device__ __forceinline__ uint32_t smem_u32(const void* p) {
    uint32_t a;
    asm("{ .reg .u64 t; cvta.to.shared.u64 t, %1; cvt.u32.u64 %0, t; }"
        : "=r"(a) : "l"(p));
    return a;
}

__device__ __forceinline__ void ldsm_x4(uint32_t& r0, uint32_t& r1,
                                        uint32_t& r2, uint32_t& r3, uint32_t addr) {
    asm volatile("ldmatrix.sync.aligned.m8n8.x4.shared.b16 {%0,%1,%2,%3}, [%4];"
                 : "=r"(r0), "=r"(r1), "=r"(r2), "=r"(r3) : "r"(addr));
}

__device__ __forceinline__ void mma16816(float* c, const uint32_t* a,
                                         uint32_t b0, uint32_t b1) {
    asm volatile(
        "mma.sync.aligned.m16n8k16.row.col.f32.bf16.bf16.f32 "
        "{%0,%1,%2,%3}, {%4,%5,%6,%7}, {%8,%9}, {%0,%1,%2,%3};"
        : "+f"(c[0]), "+f"(c[1]), "+f"(c[2]), "+f"(c[3])
        : "r"(a[0]), "r"(a[1]), "r"(a[2]), "r"(a[3]), "r"(b0), "r"(b1));
}

__device__ __forceinline__ uint32_t packbf2(float a, float b) {
    __nv_bfloat162 t = __floats2bfloat162_rn(a, b);
    return *reinterpret_cast<uint32_t*>(&t);
}

// fp32 packed FMA for the attention kernel
__device__ __forceinline__ float2 ffma2(float2 a, float2 b, float2 c) {
    float2 d;
    asm("fma.rn.f32x2 %0, %1, %2, %3;"
        : "=l"(*reinterpret_cast<unsigned long long*>(&d))
        : "l"(*reinterpret_cast<const unsigned long long*>(&a)),
          "l"(*reinterpret_cast<const unsigned long long*>(&b)),
          "l"(*reinterpret_cast<const unsigned long long*>(&c)));
    return d;
}
__device__ __forceinline__ float2 bcast2(float a) { return make_float2(a, a); }

// ---------------------------------------------------------------------------
// Weight transpose + bf16 split: W[K,N] fp32 -> hi/lo [N,K] bf16
// ---------------------------------------------------------------------------
__global__ void __launch_bounds__(256)
wsplit(const float* __restrict__ W, __nv_bfloat16* __restrict__ hi,
       __nv_bfloat16* __restrict__ lo, int K, int N)
{
    __shared__ float t[32][33];
    const int k0 = blockIdx.x * 32, n0 = blockIdx.y * 32;
    const int tx = threadIdx.x & 31, ty = threadIdx.x >> 5;   // 32x8
    #pragma unroll
    for (int i = 0; i < 32; i += 8)
        t[ty + i][tx] = W[(size_t)(k0 + ty + i) * N + n0 + tx];
    __syncthreads();
    #pragma unroll
    for (int i = 0; i < 32; i += 8) {
        float x = t[tx][ty + i];
        __nv_bfloat16 h = __float2bfloat16(x);
        __nv_bfloat16 l = __float2bfloat16(x - __bfloat162float(h));
        size_t o = (size_t)(n0 + ty + i) * K + k0 + tx;
        hi[o] = h; lo[o] = l;
    }
}

// ---------------------------------------------------------------------------
// mma.sync GEMM: C[M,512] = A[M,K] @ W[K,512] (+bias), split-bf16 3-MMA.
// CTA 128x128, BK=32, 256 threads (8 warps, 64x32 warp tiles),
// double-buffered smem (2 x 40KB), register prefetch, 1 sync/chunk.
// smem layout per buffer: bf16 [128][40] tiles (stride 80B, conflict-free).
// ---------------------------------------------------------------------------
#define GS_AH 0
#define GS_AL 10240
#define GS_BH 20480
#define GS_BL 30720
#define GS_BUF 40960
#define GEMM_SMEM (2 * GS_BUF)        // 81920 B

__global__ void __launch_bounds__(256, 1)
sgemm_mma(const float* __restrict__ A,
          const __nv_bfloat16* __restrict__ BThi,
          const __nv_bfloat16* __restrict__ BTlo,
          const float* __restrict__ bias,
          float* __restrict__ C, int K)
{
    extern __shared__ char smem[];
    const uint32_t sb = smem_u32(smem);
    const int tid  = threadIdx.x;
    const int lane = tid & 31;
    const int wid  = tid >> 5;
    const int wm   = (wid & 1) * 64;      // warp m offset in tile
    const int wn   = (wid >> 1) * 32;     // warp n offset in tile
    const int m0   = blockIdx.y * 128;
    const int n0   = blockIdx.x * 128;
    const int N    = 512;

    float acc[4][4][4];
    #pragma unroll
    for (int mi = 0; mi < 4; ++mi)
        #pragma unroll
        for (int ni = 0; ni < 4; ++ni)
            #pragma unroll
            for (int r = 0; r < 4; ++r) acc[mi][ni][r] = 0.f;

    const int nch = K >> 5;

    // ---- stage chunk 0 ----
    {
        char* buf = smem;
        #pragma unroll
        for (int i = 0; i < 4; ++i) {
            int idx = tid + i * 256;             // 1024 float4 slots
            int row = idx >> 3, g = idx & 7;
            float4 v = *(const float4*)&A[(size_t)(m0 + row) * K + g * 4];
            float hx = __bfloat162float(__float2bfloat16(v.x));
            float hy = __bfloat162float(__float2bfloat16(v.y));
            float hz = __bfloat162float(__float2bfloat16(v.z));
            float hw = __bfloat162float(__float2bfloat16(v.w));
            *(uint2*)(buf + GS_AH + row * 80 + g * 8) =
                make_uint2(packbf2(v.x, v.y), packbf2(v.z, v.w));
            *(uint2*)(buf + GS_AL + row * 80 + g * 8) =
                make_uint2(packbf2(v.x - hx, v.y - hy), packbf2(v.z - hz, v.w - hw));
        }
        #pragma unroll
        for (int i = 0; i < 2; ++i) {
            int idx = tid + i * 256;             // 512 uint4 slots
            int row = idx >> 2, g = idx & 3;
            size_t go = (size_t)(n0 + row) * K + g * 8;
            *(uint4*)(buf + GS_BH + row * 80 + g * 16) = *(const uint4*)&BThi[go];
            *(uint4*)(buf + GS_BL + row * 80 + g * 16) = *(const uint4*)&BTlo[go];
        }
    }
    __syncthreads();

    const int lr = lane & 15;                    // ldmatrix row select
    const int lc = (lane >> 4) << 3;             // ldmatrix col select (0/8)

    for (int c = 0; c < nch; ++c) {
        const uint32_t bufo = (uint32_t)((c & 1) * GS_BUF);
        const bool more = (c + 1 < nch);

        // ---- prefetch next chunk to regs ----
        float4 pa[4]; uint4 pbh[2], pbl[2];
        if (more) {
            const int k0n = (c + 1) << 5;
            #pragma unroll
            for (int i = 0; i < 4; ++i) {
                int idx = tid + i * 256;
                int row = idx >> 3, g = idx & 7;
                pa[i] = *(const float4*)&A[(size_t)(m0 + row) * K + k0n + g * 4];
            }
            #pragma unroll
            for (int i = 0; i < 2; ++i) {
                int idx = tid + i * 256;
                int row = idx >> 2, g = idx & 3;
                size_t go = (size_t)(n0 + row) * K + k0n + g * 8;
                pbh[i] = *(const uint4*)&BThi[go];
                pbl[i] = *(const uint4*)&BTlo[go];
            }
        }

        // ---- compute on current buffer ----
        #pragma unroll
        for (int ks = 0; ks < 32; ks += 16) {
            uint32_t ah[4][4], al[4][4], bh[2][4], bl[2][4];
            #pragma unroll
            for (int mi = 0; mi < 4; ++mi) {
                uint32_t off = (uint32_t)((wm + mi * 16 + lr) * 80 + (ks + lc) * 2);
                ldsm_x4(ah[mi][0], ah[mi][1], ah[mi][2], ah[mi][3], sb + bufo + GS_AH + off);
                ldsm_x4(al[mi][0], al[mi][1], al[mi][2], al[mi][3], sb + bufo + GS_AL + off);
            }
            #pragma unroll
            for (int nt = 0; nt < 2; ++nt) {
                uint32_t off = (uint32_t)((wn + nt * 16 + lr) * 80 + (ks + lc) * 2);
                ldsm_x4(bh[nt][0], bh[nt][1], bh[nt][2], bh[nt][3], sb + bufo + GS_BH + off);
                ldsm_x4(bl[nt][0], bl[nt][1], bl[nt][2], bl[nt][3], sb + bufo + GS_BL + off);
            }
            #pragma unroll
            for (int mi = 0; mi < 4; ++mi)
                #pragma unroll
                for (int ni = 0; ni < 4; ++ni) {
                    int nt = ni >> 1, sel = ni & 1;
                    mma16816(acc[mi][ni], ah[mi], bh[nt][sel], bh[nt][sel + 2]);
                    mma16816(acc[mi][ni], ah[mi], bl[nt][sel], bl[nt][sel + 2]);
                    mma16816(acc[mi][ni], al[mi], bh[nt][sel], bh[nt][sel + 2]);
                }
        }

        // ---- store prefetched chunk into other buffer ----
        if (more) {
            char* buf = smem + ((c + 1) & 1) * GS_BUF;
            __syncthreads();   // all warps done reading before overwrite? (other buffer: not needed, but cheap safety for reuse across iters)
            #pragma unroll
            for (int i = 0; i < 4; ++i) {
                int idx = tid + i * 256;
                int row = idx >> 3, g = idx & 7;
                float4 v = pa[i];
                float hx = __bfloat162float(__float2bfloat16(v.x));
                float hy = __bfloat162float(__float2bfloat16(v.y));
                float hz = __bfloat162float(__float2bfloat16(v.z));
                float hw = __bfloat162float(__float2bfloat16(v.w));
                *(uint2*)(buf + GS_AH + row * 80 + g * 8) =
                    make_uint2(packbf2(v.x, v.y), packbf2(v.z, v.w));
                *(uint2*)(buf + GS_AL + row * 80 + g * 8) =
                    make_uint2(packbf2(v.x - hx, v.y - hy), packbf2(v.z - hz, v.w - hw));
            }
            #pragma unroll
            for (int i = 0; i < 2; ++i) {
                int idx = tid + i * 256;
                int row = idx >> 2, g = idx & 3;
                *(uint4*)(buf + GS_BH + row * 80 + g * 16) = pbh[i];
                *(uint4*)(buf + GS_BL + row * 80 + g * 16) = pbl[i];
            }
            __syncthreads();
        }
    }

    // ---- epilogue ----
    const int qrow = lane >> 2;           // 0..7
    const int qcol = (lane & 3) * 2;      // 0,2,4,6
    #pragma unroll
    for (int mi = 0; mi < 4; ++mi) {
        #pragma unroll
        for (int ni = 0; ni < 4; ++ni) {
            int row0 = m0 + wm + mi * 16 + qrow;
            int col  = n0 + wn + ni * 8 + qcol;
            float2 o0 = make_float2(acc[mi][ni][0], acc[mi][ni][1]);
            float2 o1 = make_float2(acc[mi][ni][2], acc[mi][ni][3]);
            if (bias) {
                float2 bb = *(const float2*)&bias[col];
                o0.x += bb.x; o0.y += bb.y;
                o1.x += bb.x; o1.y += bb.y;
            }
            *(float2*)&C[(size_t)row0 * N + col]       = o0;
            *(float2*)&C[(size_t)(row0 + 8) * N + col] = o1;
        }
    }
}

// ---------------------------------------------------------------------------
// Flash attention (unchanged, passing at 432us): 128x128 tile, fp32 FFMA2.
// ---------------------------------------------------------------------------
#define LDP  132
#define LDVV 68
#define ATTN_SMEM_BYTES ((64*LDP + 64*LDP + 128*LDVV + 128*LDP) * 4)

#define SEL(r, lc) (((lc) & 1) ? sacc[r][(lc) >> 1].y : sacc[r][(lc) >> 1].x)

__global__ void __launch_bounds__(256, 1)
attn_kernel(const float* __restrict__ q, const float* __restrict__ k,
            const float* __restrict__ v, float* __restrict__ o)
{
    extern __shared__ float sm[];
    float* Qt = sm;
    float* Kt = Qt + 64 * LDP;
    float* Vs = Kt + 64 * LDP;
    float* Pt = Vs + 128 * LDVV;

    const int tid = threadIdx.x;
    const int tx  = tid & 15;
    const int ty  = tid >> 4;
    const int rA  = ty * 4;
    const int rB  = 64 + ty * 4;
    const int cA  = tx * 4;
    const int cB  = 64 + tx * 4;

    const int bh = blockIdx.y;
    const int b  = bh >> 3;
    const int h  = bh & 7;
    const int qbase = b * NQ + blockIdx.x * 128;
    const int kbase = b * NK;
    const int hcol  = h * DHEAD;

    #pragma unroll
    for (int it = 0; it < 8; ++it) {
        int idx = tid + it * 256;
        int i   = idx >> 4;
        int d4  = (idx & 15) << 2;
        float4 qv = *(const float4*)&q[(size_t)(qbase + i) * INNER + hcol + d4];
        Qt[(d4 + 0) * LDP + i] = qv.x * SCALE_;
        Qt[(d4 + 1) * LDP + i] = qv.y * SCALE_;
        Qt[(d4 + 2) * LDP + i] = qv.z * SCALE_;
        Qt[(d4 + 3) * LDP + i] = qv.w * SCALE_;
    }

    float  mrow[8], lrow[8];
    float2 oacc[8][2];
    #pragma unroll
    for (int r = 0; r < 8; ++r) {
        mrow[r] = -CUDART_INF_F;
        lrow[r] = 0.f;
        oacc[r][0] = make_float2(0.f, 0.f);
        oacc[r][1] = make_float2(0.f, 0.f);
    }

    for (int jt = 0; jt < NK / 128; ++jt) {
        __syncthreads();
        const int krow0 = kbase + jt * 128;
        #pragma unroll
        for (int it = 0; it < 8; ++it) {
            int idx = tid + it * 256;
            int j   = idx >> 4;
            int d4  = (idx & 15) << 2;
            float4 kv = *(const float4*)&k[(size_t)(krow0 + j) * INNER + hcol + d4];
            Kt[(d4 + 0) * LDP + j] = kv.x;
            Kt[(d4 + 1) * LDP + j] = kv.y;
            Kt[(d4 + 2) * LDP + j] = kv.z;
            Kt[(d4 + 3) * LDP + j] = kv.w;
            *(float4*)&Vs[j * LDVV + d4] =
                *(const float4*)&v[(size_t)(krow0 + j) * INNER + hcol + d4];
        }
        __syncthreads();

        float2 sacc[8][4];
        #pragma unroll
        for (int r = 0; r < 8; ++r)
            #pragma unroll
            for (int c = 0; c < 4; ++c) sacc[r][c] = make_float2(0.f, 0.f);

        #pragma unroll 4
        for (int d = 0; d < 64; ++d) {
            float4 qa = *(const float4*)&Qt[d * LDP + rA];
            float4 qb = *(const float4*)&Qt[d * LDP + rB];
            float4 ka = *(const float4*)&Kt[d * LDP + cA];
            float4 kb = *(const float4*)&Kt[d * LDP + cB];
            float  av[8] = {qa.x, qa.y, qa.z, qa.w, qb.x, qb.y, qb.z, qb.w};
            float2 bv[4] = {make_float2(ka.x, ka.y), make_float2(ka.z, ka.w),
                            make_float2(kb.x, kb.y), make_float2(kb.z, kb.w)};
            #pragma unroll
            for (int r = 0; r < 8; ++r) {
                float2 ar = bcast2(av[r]);
                #pragma unroll
                for (int c = 0; c < 4; ++c)
                    sacc[r][c] = ffma2(ar, bv[c], sacc[r][c]);
            }
        }

        #pragma unroll
        for (int r = 0; r < 8; ++r) {
            float rmax = fmaxf(fmaxf(fmaxf(sacc[r][0].x, sacc[r][0].y),
                                     fmaxf(sacc[r][1].x, sacc[r][1].y)),
                               fmaxf(fmaxf(sacc[r][2].x, sacc[r][2].y),
                                     fmaxf(sacc[r][3].x, sacc[r][3].y)));
            #pragma unroll
            for (int off = 1; off < 16; off <<= 1)
                rmax = fmaxf(rmax, __shfl_xor_sync(0xffffffffu, rmax, off));
            float nm    = fmaxf(mrow[r], rmax);
            float alpha = __expf(mrow[r] - nm);
            mrow[r] = nm;

            float rsum = 0.f;
            #pragma unroll
            for (int c = 0; c < 4; ++c) {
                sacc[r][c].x = __expf(sacc[r][c].x - nm);
                sacc[r][c].y = __expf(sacc[r][c].y - nm);
                rsum += sacc[r][c].x + sacc[r][c].y;
            }
            #pragma unroll
            for (int off = 1; off < 16; off <<= 1)
                rsum += __shfl_xor_sync(0xffffffffu, rsum, off);

            lrow[r] = lrow[r] * alpha + rsum;
            oacc[r][0].x *= alpha; oacc[r][0].y *= alpha;
            oacc[r][1].x *= alpha; oacc[r][1].y *= alpha;
        }

        #pragma unroll
        for (int lc = 0; lc < 8; ++lc) {
            int pc = (lc < 4) ? (cA + lc) : (cB + lc - 4);
            float4 t0 = make_float4(SEL(0, lc), SEL(1, lc), SEL(2, lc), SEL(3, lc));
            float4 t1 = make_float4(SEL(4, lc), SEL(5, lc), SEL(6, lc), SEL(7, lc));
            *(float4*)&Pt[pc * LDP + rA] = t0;
            *(float4*)&Pt[pc * LDP + rB] = t1;
        }
        __syncthreads();

        #pragma unroll 4
        for (int j = 0; j < 128; ++j) {
            float4 p0 = *(const float4*)&Pt[j * LDP + rA];
            float4 p1 = *(const float4*)&Pt[j * LDP + rB];
            float4 vv = *(const float4*)&Vs[j * LDVV + cA];
            float2 v01 = make_float2(vv.x, vv.y);
            float2 v23 = make_float2(vv.z, vv.w);
            float  pr[8] = {p0.x, p0.y, p0.z, p0.w, p1.x, p1.y, p1.z, p1.w};
            #pragma unroll
            for (int r = 0; r < 8; ++r) {
                float2 p2 = bcast2(pr[r]);
                oacc[r][0] = ffma2(p2, v01, oacc[r][0]);
                oacc[r][1] = ffma2(p2, v23, oacc[r][1]);
            }
        }
    }

    #pragma unroll
    for (int r = 0; r < 8; ++r) {
        float inv = 1.0f / lrow[r];
        int   row = qbase + ((r < 4) ? (rA + r) : (rB + r - 4));
        *(float4*)&o[(size_t)row * INNER + hcol + cA] =
            make_float4(oacc[r][0].x * inv, oacc[r][0].y * inv,
                        oacc[r][1].x * inv, oacc[r][1].y * inv);
    }
}

// ---------------------------------------------------------------------------
// Launch
// ---------------------------------------------------------------------------
extern "C" void kernel_launch(void* const* d_in, const int* in_sizes, int n_in,
                              void* d_out, int out_size)
{
    (void)in_sizes; (void)n_in; (void)out_size;
    const float* x   = (const float*)d_in[0];
    const float* ctx = (const float*)d_in[1];
    const float* Wq  = (const float*)d_in[2];
    const float* Wk  = (const float*)d_in[3];
    const float* Wv  = (const float*)d_in[4];
    const float* Wo  = (const float*)d_in[5];
    const float* bo  = (const float*)d_in[6];
    float* out = (float*)d_out;

    float *q, *k, *v, *ao;
    __nv_bfloat16 *wthi, *wtlo;
    cudaGetSymbolAddress((void**)&q,    g_q);
    cudaGetSymbolAddress((void**)&k,    g_k);
    cudaGetSymbolAddress((void**)&v,    g_v);
    cudaGetSymbolAddress((void**)&ao,   g_ao);
    cudaGetSymbolAddress((void**)&wthi, g_wthi);
    cudaGetSymbolAddress((void**)&wtlo, g_wtlo);

    (void)cudaFuncSetAttribute(attn_kernel,
                               cudaFuncAttributeMaxDynamicSharedMemorySize,
                               ATTN_SMEM_BYTES);
    (void)cudaFuncSetAttribute(sgemm_mma,
                               cudaFuncAttributeMaxDynamicSharedMemorySize,
                               GEMM_SMEM);

    // weight transpose + split (tiny)
    wsplit<<<dim3(DQ/32,    INNER/32), 256>>>(Wq, wthi + OFF_WQ, wtlo + OFF_WQ, DQ,    INNER);
    wsplit<<<dim3(DC/32,    INNER/32), 256>>>(Wk, wthi + OFF_WK, wtlo + OFF_WK, DC,    INNER);
    wsplit<<<dim3(DC/32,    INNER/32), 256>>>(Wv, wthi + OFF_WV, wtlo + OFF_WV, DC,    INNER);
    wsplit<<<dim3(INNER/32, DQ/32),    256>>>(Wo, wthi + OFF_WO, wtlo + OFF_WO, INNER, DQ);

    // projections on tensor cores (mma.sync bf16 split)
    sgemm_mma<<<dim3(4, MQ_ALL/128), 256, GEMM_SMEM>>>(x,   wthi + OFF_WQ, wtlo + OFF_WQ, nullptr, q, DQ);
    sgemm_mma<<<dim3(4, MK_ALL/128), 256, GEMM_SMEM>>>(ctx, wthi + OFF_WK, wtlo + OFF_WK, nullptr, k, DC);
    sgemm_mma<<<dim3(4, MK_ALL/128), 256, GEMM_SMEM>>>(ctx, wthi + OFF_WV, wtlo + OFF_WV, nullptr, v, DC);

    // attention (fp32)
    attn_kernel<<<dim3(NQ / 128, B_ * HEADS), 256, ATTN_SMEM_BYTES>>>(q, k, v, ao);

    // output projection + bias
    sgemm_mma<<<dim3(4, MQ_ALL/128), 256, GEMM_SMEM>>>(ao, wthi + OFF_WO, wtlo + OFF_WO, bo, out, DQ);
}

// round 8
// speedup vs baseline: 1.8551x; 1.3480x over previous
#include <cuda_runtime.h>
#include <cuda_bf16.h>
#include <math_constants.h>
#include <cstdint>

// ---------------------------------------------------------------------------
// CrossAttention: out = softmax((xWq)(ctxWk)^T * scale) (ctxWv) Wo + bo
// B=4, Nq=2048, Dq=512, Nk=1024, Dc=768, H=8, d=64, inner=512
// Round 6: attention ported to mma.sync bf16 split (3-MMA both GEMMs,
// P kept in registers). Projections unchanged from R5 (passing, 1.17e-5).
// ---------------------------------------------------------------------------

#define B_     4
#define NQ     2048
#define NK     1024
#define DQ     512
#define DC     768
#define HEADS  8
#define DHEAD  64
#define INNER  512
#define MQ_ALL (B_*NQ)        // 8192
#define MK_ALL (B_*NK)        // 4096
#define SCALE_ 0.125f

__device__ float g_q [MQ_ALL * INNER];
__device__ float g_k [MK_ALL * INNER];
__device__ float g_v [MK_ALL * INNER];
__device__ float g_ao[MQ_ALL * INNER];

#define OFF_WQ 0
#define OFF_WK (512*512)
#define OFF_WV (OFF_WK + 512*768)
#define OFF_WO (OFF_WV + 512*768)
#define WT_TOTAL (OFF_WO + 512*512)
__device__ __nv_bfloat16 g_wthi[WT_TOTAL];
__device__ __nv_bfloat16 g_wtlo[WT_TOTAL];

// ---------------------------------------------------------------------------
// helpers
// ---------------------------------------------------------------------------
__device__ __forceinline__ uint32_t smem_u32(const void* p) {
    uint32_t a;
    asm("{ .reg .u64 t; cvta.to.shared.u64 t, %1; cvt.u32.u64 %0, t; }"
        : "=r"(a) : "l"(p));
    return a;
}
__device__ __forceinline__ void ldsm_x4(uint32_t& r0, uint32_t& r1,
                                        uint32_t& r2, uint32_t& r3, uint32_t addr) {
    asm volatile("ldmatrix.sync.aligned.m8n8.x4.shared.b16 {%0,%1,%2,%3}, [%4];"
                 : "=r"(r0), "=r"(r1), "=r"(r2), "=r"(r3) : "r"(addr));
}
__device__ __forceinline__ void mma16816(float* c, const uint32_t* a,
                                         uint32_t b0, uint32_t b1) {
    asm volatile(
        "mma.sync.aligned.m16n8k16.row.col.f32.bf16.bf16.f32 "
        "{%0,%1,%2,%3}, {%4,%5,%6,%7}, {%8,%9}, {%0,%1,%2,%3};"
        : "+f"(c[0]), "+f"(c[1]), "+f"(c[2]), "+f"(c[3])
        : "r"(a[0]), "r"(a[1]), "r"(a[2]), "r"(a[3]), "r"(b0), "r"(b1));
}
__device__ __forceinline__ uint32_t packbf2(float a, float b) {
    __nv_bfloat162 t = __floats2bfloat162_rn(a, b);
    return *reinterpret_cast<uint32_t*>(&t);
}
__device__ __forceinline__ float bfhi(float x) {
    return __bfloat162float(__float2bfloat16(x));
}

// ---------------------------------------------------------------------------
// Weight transpose + bf16 split: W[K,N] fp32 -> hi/lo [N,K] bf16
// ---------------------------------------------------------------------------
__global__ void __launch_bounds__(256)
wsplit(const float* __restrict__ W, __nv_bfloat16* __restrict__ hi,
       __nv_bfloat16* __restrict__ lo, int K, int N)
{
    __shared__ float t[32][33];
    const int k0 = blockIdx.x * 32, n0 = blockIdx.y * 32;
    const int tx = threadIdx.x & 31, ty = threadIdx.x >> 5;
    #pragma unroll
    for (int i = 0; i < 32; i += 8)
        t[ty + i][tx] = W[(size_t)(k0 + ty + i) * N + n0 + tx];
    __syncthreads();
    #pragma unroll
    for (int i = 0; i < 32; i += 8) {
        float x = t[tx][ty + i];
        __nv_bfloat16 h = __float2bfloat16(x);
        __nv_bfloat16 l = __float2bfloat16(x - __bfloat162float(h));
        size_t o = (size_t)(n0 + ty + i) * K + k0 + tx;
        hi[o] = h; lo[o] = l;
    }
}

// ---------------------------------------------------------------------------
// mma.sync GEMM (unchanged from R5, passing): C = A @ W (+bias), split 3-MMA
// ---------------------------------------------------------------------------
#define GS_AH 0
#define GS_AL 10240
#define GS_BH 20480
#define GS_BL 30720
#define GS_BUF 40960
#define GEMM_SMEM (2 * GS_BUF)

__global__ void __launch_bounds__(256, 1)
sgemm_mma(const float* __restrict__ A,
          const __nv_bfloat16* __restrict__ BThi,
          const __nv_bfloat16* __restrict__ BTlo,
          const float* __restrict__ bias,
          float* __restrict__ C, int K)
{
    extern __shared__ char smem[];
    const uint32_t sb = smem_u32(smem);
    const int tid  = threadIdx.x;
    const int lane = tid & 31;
    const int wid  = tid >> 5;
    const int wm   = (wid & 1) * 64;
    const int wn   = (wid >> 1) * 32;
    const int m0   = blockIdx.y * 128;
    const int n0   = blockIdx.x * 128;
    const int N    = 512;

    float acc[4][4][4];
    #pragma unroll
    for (int mi = 0; mi < 4; ++mi)
        #pragma unroll
        for (int ni = 0; ni < 4; ++ni)
            #pragma unroll
            for (int r = 0; r < 4; ++r) acc[mi][ni][r] = 0.f;

    const int nch = K >> 5;

    {
        char* buf = smem;
        #pragma unroll
        for (int i = 0; i < 4; ++i) {
            int idx = tid + i * 256;
            int row = idx >> 3, g = idx & 7;
            float4 v = *(const float4*)&A[(size_t)(m0 + row) * K + g * 4];
            *(uint2*)(buf + GS_AH + row * 80 + g * 8) =
                make_uint2(packbf2(v.x, v.y), packbf2(v.z, v.w));
            *(uint2*)(buf + GS_AL + row * 80 + g * 8) =
                make_uint2(packbf2(v.x - bfhi(v.x), v.y - bfhi(v.y)),
                           packbf2(v.z - bfhi(v.z), v.w - bfhi(v.w)));
        }
        #pragma unroll
        for (int i = 0; i < 2; ++i) {
            int idx = tid + i * 256;
            int row = idx >> 2, g = idx & 3;
            size_t go = (size_t)(n0 + row) * K + g * 8;
            *(uint4*)(buf + GS_BH + row * 80 + g * 16) = *(const uint4*)&BThi[go];
            *(uint4*)(buf + GS_BL + row * 80 + g * 16) = *(const uint4*)&BTlo[go];
        }
    }
    __syncthreads();

    const int lr = lane & 15;
    const int lc = (lane >> 4) << 3;

    for (int c = 0; c < nch; ++c) {
        const uint32_t bufo = (uint32_t)((c & 1) * GS_BUF);
        const bool more = (c + 1 < nch);

        float4 pa[4]; uint4 pbh[2], pbl[2];
        if (more) {
            const int k0n = (c + 1) << 5;
            #pragma unroll
            for (int i = 0; i < 4; ++i) {
                int idx = tid + i * 256;
                int row = idx >> 3, g = idx & 7;
                pa[i] = *(const float4*)&A[(size_t)(m0 + row) * K + k0n + g * 4];
            }
            #pragma unroll
            for (int i = 0; i < 2; ++i) {
                int idx = tid + i * 256;
                int row = idx >> 2, g = idx & 3;
                size_t go = (size_t)(n0 + row) * K + k0n + g * 8;
                pbh[i] = *(const uint4*)&BThi[go];
                pbl[i] = *(const uint4*)&BTlo[go];
            }
        }

        #pragma unroll
        for (int ks = 0; ks < 32; ks += 16) {
            uint32_t ah[4][4], al[4][4], bh[2][4], bl[2][4];
            #pragma unroll
            for (int mi = 0; mi < 4; ++mi) {
                uint32_t off = (uint32_t)((wm + mi * 16 + lr) * 80 + (ks + lc) * 2);
                ldsm_x4(ah[mi][0], ah[mi][1], ah[mi][2], ah[mi][3], sb + bufo + GS_AH + off);
                ldsm_x4(al[mi][0], al[mi][1], al[mi][2], al[mi][3], sb + bufo + GS_AL + off);
            }
            #pragma unroll
            for (int nt = 0; nt < 2; ++nt) {
                uint32_t off = (uint32_t)((wn + nt * 16 + lr) * 80 + (ks + lc) * 2);
                ldsm_x4(bh[nt][0], bh[nt][1], bh[nt][2], bh[nt][3], sb + bufo + GS_BH + off);
                ldsm_x4(bl[nt][0], bl[nt][1], bl[nt][2], bl[nt][3], sb + bufo + GS_BL + off);
            }
            #pragma unroll
            for (int mi = 0; mi < 4; ++mi)
                #pragma unroll
                for (int ni = 0; ni < 4; ++ni) {
                    int nt = ni >> 1, sel = ni & 1;
                    mma16816(acc[mi][ni], ah[mi], bh[nt][sel], bh[nt][sel + 2]);
                    mma16816(acc[mi][ni], ah[mi], bl[nt][sel], bl[nt][sel + 2]);
                    mma16816(acc[mi][ni], al[mi], bh[nt][sel], bh[nt][sel + 2]);
                }
        }

        if (more) {
            char* buf = smem + ((c + 1) & 1) * GS_BUF;
            __syncthreads();
            #pragma unroll
            for (int i = 0; i < 4; ++i) {
                int idx = tid + i * 256;
                int row = idx >> 3, g = idx & 7;
                float4 v = pa[i];
                *(uint2*)(buf + GS_AH + row * 80 + g * 8) =
                    make_uint2(packbf2(v.x, v.y), packbf2(v.z, v.w));
                *(uint2*)(buf + GS_AL + row * 80 + g * 8) =
                    make_uint2(packbf2(v.x - bfhi(v.x), v.y - bfhi(v.y)),
                               packbf2(v.z - bfhi(v.z), v.w - bfhi(v.w)));
            }
            #pragma unroll
            for (int i = 0; i < 2; ++i) {
                int idx = tid + i * 256;
                int row = idx >> 2, g = idx & 3;
                *(uint4*)(buf + GS_BH + row * 80 + g * 16) = pbh[i];
                *(uint4*)(buf + GS_BL + row * 80 + g * 16) = pbl[i];
            }
            __syncthreads();
        }
    }

    const int qrow = lane >> 2;
    const int qcol = (lane & 3) * 2;
    #pragma unroll
    for (int mi = 0; mi < 4; ++mi) {
        #pragma unroll
        for (int ni = 0; ni < 4; ++ni) {
            int row0 = m0 + wm + mi * 16 + qrow;
            int col  = n0 + wn + ni * 8 + qcol;
            float2 o0 = make_float2(acc[mi][ni][0], acc[mi][ni][1]);
            float2 o1 = make_float2(acc[mi][ni][2], acc[mi][ni][3]);
            if (bias) {
                float2 bb = *(const float2*)&bias[col];
                o0.x += bb.x; o0.y += bb.y;
                o1.x += bb.x; o1.y += bb.y;
            }
            *(float2*)&C[(size_t)row0 * N + col]       = o0;
            *(float2*)&C[(size_t)(row0 + 8) * N + col] = o1;
        }
    }
}

// ---------------------------------------------------------------------------
// Flash attention on mma.sync bf16 split.
// CTA = (b,h) x 128 q-rows; 8 warps x 16 rows; KV tiled by 128.
// smem: KH/KL [128][72] bf16 (stride 144B), VH/VL (V^T) [64][136] (stride 272B).
// Q staged through KH/KL then held in registers as hi/lo fragments.
// ---------------------------------------------------------------------------
#define AT_KH 0
#define AT_KL 18432
#define AT_VH 36864
#define AT_VL 54272
#define ATTN_SMEM 71680
#define KSTR 144
#define VSTR 272

__global__ void __launch_bounds__(256, 1)
attn_mma(const float* __restrict__ q, const float* __restrict__ k,
         const float* __restrict__ v, float* __restrict__ o)
{
    extern __shared__ char smem[];
    const uint32_t sb = smem_u32(smem);
    const int tid  = threadIdx.x;
    const int lane = tid & 31;
    const int wid  = tid >> 5;
    const int wq   = wid * 16;
    const int lr   = lane & 15;
    const int lc   = (lane >> 4) << 3;

    const int bh = blockIdx.y;
    const int b  = bh >> 3;
    const int h  = bh & 7;
    const int qbase = b * NQ + blockIdx.x * 128;
    const int kbase = b * NK;
    const int hcol  = h * DHEAD;

    // ---- stage Q (scaled, split) through K smem area ----
    #pragma unroll
    for (int i = 0; i < 8; ++i) {
        int idx = tid + i * 256;
        int row = idx >> 4, g = idx & 15;
        float4 qv = *(const float4*)&q[(size_t)(qbase + row) * INNER + hcol + g * 4];
        qv.x *= SCALE_; qv.y *= SCALE_; qv.z *= SCALE_; qv.w *= SCALE_;
        *(uint2*)(smem + AT_KH + row * KSTR + g * 8) =
            make_uint2(packbf2(qv.x, qv.y), packbf2(qv.z, qv.w));
        *(uint2*)(smem + AT_KL + row * KSTR + g * 8) =
            make_uint2(packbf2(qv.x - bfhi(qv.x), qv.y - bfhi(qv.y)),
                       packbf2(qv.z - bfhi(qv.z), qv.w - bfhi(qv.w)));
    }
    __syncthreads();

    uint32_t qh[4][4], ql[4][4];
    #pragma unroll
    for (int ks = 0; ks < 4; ++ks) {
        uint32_t off = (uint32_t)((wq + lr) * KSTR + (ks * 16 + lc) * 2);
        ldsm_x4(qh[ks][0], qh[ks][1], qh[ks][2], qh[ks][3], sb + AT_KH + off);
        ldsm_x4(ql[ks][0], ql[ks][1], ql[ks][2], ql[ks][3], sb + AT_KL + off);
    }

    float mrow[2] = {-CUDART_INF_F, -CUDART_INF_F};
    float lrow[2] = {0.f, 0.f};
    float oacc[8][4];
    #pragma unroll
    for (int ni = 0; ni < 8; ++ni)
        #pragma unroll
        for (int r = 0; r < 4; ++r) oacc[ni][r] = 0.f;

    for (int jt = 0; jt < NK / 128; ++jt) {
        __syncthreads();   // Q frags read / previous tile reads complete
        const int krow0 = kbase + jt * 128;

        // K tile -> split smem [j][d]
        #pragma unroll
        for (int i = 0; i < 8; ++i) {
            int idx = tid + i * 256;
            int row = idx >> 4, g = idx & 15;
            float4 kv = *(const float4*)&k[(size_t)(krow0 + row) * INNER + hcol + g * 4];
            *(uint2*)(smem + AT_KH + row * KSTR + g * 8) =
                make_uint2(packbf2(kv.x, kv.y), packbf2(kv.z, kv.w));
            *(uint2*)(smem + AT_KL + row * KSTR + g * 8) =
                make_uint2(packbf2(kv.x - bfhi(kv.x), kv.y - bfhi(kv.y)),
                           packbf2(kv.z - bfhi(kv.z), kv.w - bfhi(kv.w)));
        }
        // V tile -> transposed split smem [d][j]
        __nv_bfloat16* VH = (__nv_bfloat16*)(smem + AT_VH);
        __nv_bfloat16* VL = (__nv_bfloat16*)(smem + AT_VL);
        #pragma unroll
        for (int i = 0; i < 8; ++i) {
            int idx = tid + i * 256;
            int j = idx >> 4, g = idx & 15;
            int d4 = g * 4;
            float4 vv = *(const float4*)&v[(size_t)(krow0 + j) * INNER + hcol + d4];
            float vals[4] = {vv.x, vv.y, vv.z, vv.w};
            #pragma unroll
            for (int t = 0; t < 4; ++t) {
                float x = vals[t];
                __nv_bfloat16 hx = __float2bfloat16(x);
                VH[(d4 + t) * 136 + j] = hx;
                VL[(d4 + t) * 136 + j] = __float2bfloat16(x - __bfloat162float(hx));
            }
        }
        __syncthreads();

        // ---- S = Q K^T (3-MMA split) ----
        float sacc[16][4];
        #pragma unroll
        for (int ni = 0; ni < 16; ++ni)
            #pragma unroll
            for (int r = 0; r < 4; ++r) sacc[ni][r] = 0.f;

        #pragma unroll
        for (int ks = 0; ks < 4; ++ks) {
            #pragma unroll
            for (int nt = 0; nt < 8; ++nt) {
                uint32_t off = (uint32_t)((nt * 16 + lr) * KSTR + (ks * 16 + lc) * 2);
                uint32_t kh0, kh1, kh2, kh3, kl0, kl1, kl2, kl3;
                ldsm_x4(kh0, kh1, kh2, kh3, sb + AT_KH + off);
                ldsm_x4(kl0, kl1, kl2, kl3, sb + AT_KL + off);
                uint32_t khr[4] = {kh0, kh1, kh2, kh3};
                uint32_t klr[4] = {kl0, kl1, kl2, kl3};
                #pragma unroll
                for (int sel = 0; sel < 2; ++sel) {
                    int ni = nt * 2 + sel;
                    mma16816(sacc[ni], qh[ks], khr[sel], khr[sel + 2]);
                    mma16816(sacc[ni], qh[ks], klr[sel], klr[sel + 2]);
                    mma16816(sacc[ni], ql[ks], khr[sel], khr[sel + 2]);
                }
            }
        }

        // ---- online softmax (rows r=lane>>2 and r+8; reduce over lane quad) ----
        #pragma unroll
        for (int half = 0; half < 2; ++half) {
            const int c0 = half * 2, c1 = half * 2 + 1;
            float rmax = -CUDART_INF_F;
            #pragma unroll
            for (int ni = 0; ni < 16; ++ni)
                rmax = fmaxf(rmax, fmaxf(sacc[ni][c0], sacc[ni][c1]));
            rmax = fmaxf(rmax, __shfl_xor_sync(0xffffffffu, rmax, 1));
            rmax = fmaxf(rmax, __shfl_xor_sync(0xffffffffu, rmax, 2));
            float nm    = fmaxf(mrow[half], rmax);
            float alpha = __expf(mrow[half] - nm);
            mrow[half] = nm;

            float rsum = 0.f;
            #pragma unroll
            for (int ni = 0; ni < 16; ++ni) {
                sacc[ni][c0] = __expf(sacc[ni][c0] - nm);
                sacc[ni][c1] = __expf(sacc[ni][c1] - nm);
                rsum += sacc[ni][c0] + sacc[ni][c1];
            }
            rsum += __shfl_xor_sync(0xffffffffu, rsum, 1);
            rsum += __shfl_xor_sync(0xffffffffu, rsum, 2);

            lrow[half] = lrow[half] * alpha + rsum;
            #pragma unroll
            for (int ni = 0; ni < 8; ++ni) {
                oacc[ni][c0] *= alpha;
                oacc[ni][c1] *= alpha;
            }
        }

        // ---- O += P V (P from registers, 3-MMA split) ----
        #pragma unroll
        for (int ks2 = 0; ks2 < 8; ++ks2) {
            const int e = ks2 * 2, od = ks2 * 2 + 1;
            float p00 = sacc[e][0],  p01 = sacc[e][1],  p10 = sacc[e][2],  p11 = sacc[e][3];
            float r00 = sacc[od][0], r01 = sacc[od][1], r10 = sacc[od][2], r11 = sacc[od][3];
            uint32_t ph[4] = {packbf2(p00, p01), packbf2(p10, p11),
                              packbf2(r00, r01), packbf2(r10, r11)};
            uint32_t pl[4] = {packbf2(p00 - bfhi(p00), p01 - bfhi(p01)),
                              packbf2(p10 - bfhi(p10), p11 - bfhi(p11)),
                              packbf2(r00 - bfhi(r00), r01 - bfhi(r01)),
                              packbf2(r10 - bfhi(r10), r11 - bfhi(r11))};
            #pragma unroll
            for (int vt = 0; vt < 4; ++vt) {
                uint32_t off = (uint32_t)((vt * 16 + lr) * VSTR + (ks2 * 16 + lc) * 2);
                uint32_t vh0, vh1, vh2, vh3, vl0, vl1, vl2, vl3;
                ldsm_x4(vh0, vh1, vh2, vh3, sb + AT_VH + off);
                ldsm_x4(vl0, vl1, vl2, vl3, sb + AT_VL + off);
                uint32_t vhr[4] = {vh0, vh1, vh2, vh3};
                uint32_t vlr[4] = {vl0, vl1, vl2, vl3};
                #pragma unroll
                for (int sel = 0; sel < 2; ++sel) {
                    int ni = vt * 2 + sel;
                    mma16816(oacc[ni], ph, vhr[sel], vhr[sel + 2]);
                    mma16816(oacc[ni], pl, vhr[sel], vhr[sel + 2]);
                    mma16816(oacc[ni], ph, vlr[sel], vlr[sel + 2]);
                }
            }
        }
    }

    // ---- normalize + write (head-merged layout) ----
    const float inv0 = 1.0f / lrow[0];
    const float inv1 = 1.0f / lrow[1];
    const int row0 = qbase + wq + (lane >> 2);
    #pragma unroll
    for (int ni = 0; ni < 8; ++ni) {
        int col = hcol + ni * 8 + (lane & 3) * 2;
        *(float2*)&o[(size_t)row0 * INNER + col] =
            make_float2(oacc[ni][0] * inv0, oacc[ni][1] * inv0);
        *(float2*)&o[(size_t)(row0 + 8) * INNER + col] =
            make_float2(oacc[ni][2] * inv1, oacc[ni][3] * inv1);
    }
}

// ---------------------------------------------------------------------------
// Launch
// ---------------------------------------------------------------------------
extern "C" void kernel_launch(void* const* d_in, const int* in_sizes, int n_in,
                              void* d_out, int out_size)
{
    (void)in_sizes; (void)n_in; (void)out_size;
    const float* x   = (const float*)d_in[0];
    const float* ctx = (const float*)d_in[1];
    const float* Wq  = (const float*)d_in[2];
    const float* Wk  = (const float*)d_in[3];
    const float* Wv  = (const float*)d_in[4];
    const float* Wo  = (const float*)d_in[5];
    const float* bo  = (const float*)d_in[6];
    float* out = (float*)d_out;

    float *q, *k, *v, *ao;
    __nv_bfloat16 *wthi, *wtlo;
    cudaGetSymbolAddress((void**)&q,    g_q);
    cudaGetSymbolAddress((void**)&k,    g_k);
    cudaGetSymbolAddress((void**)&v,    g_v);
    cudaGetSymbolAddress((void**)&ao,   g_ao);
    cudaGetSymbolAddress((void**)&wthi, g_wthi);
    cudaGetSymbolAddress((void**)&wtlo, g_wtlo);

    (void)cudaFuncSetAttribute(attn_mma,
                               cudaFuncAttributeMaxDynamicSharedMemorySize,
                               ATTN_SMEM);
    (void)cudaFuncSetAttribute(sgemm_mma,
                               cudaFuncAttributeMaxDynamicSharedMemorySize,
                               GEMM_SMEM);

    wsplit<<<dim3(DQ/32,    INNER/32), 256>>>(Wq, wthi + OFF_WQ, wtlo + OFF_WQ, DQ,    INNER);
    wsplit<<<dim3(DC/32,    INNER/32), 256>>>(Wk, wthi + OFF_WK, wtlo + OFF_WK, DC,    INNER);
    wsplit<<<dim3(DC/32,    INNER/32), 256>>>(Wv, wthi + OFF_WV, wtlo + OFF_WV, DC,    INNER);
    wsplit<<<dim3(INNER/32, DQ/32),    256>>>(Wo, wthi + OFF_WO, wtlo + OFF_WO, INNER, DQ);

    sgemm_mma<<<dim3(4, MQ_ALL/128), 256, GEMM_SMEM>>>(x,   wthi + OFF_WQ, wtlo + OFF_WQ, nullptr, q, DQ);
    sgemm_mma<<<dim3(4, MK_ALL/128), 256, GEMM_SMEM>>>(ctx, wthi + OFF_WK, wtlo + OFF_WK, nullptr, k, DC);
    sgemm_mma<<<dim3(4, MK_ALL/128), 256, GEMM_SMEM>>>(ctx, wthi + OFF_WV, wtlo + OFF_WV, nullptr, v, DC);

    attn_mma<<<dim3(NQ / 128, B_ * HEADS), 256, ATTN_SMEM>>>(q, k, v, ao);

    sgemm_mma<<<dim3(4, MQ_ALL/128), 256, GEMM_SMEM>>>(ao, wthi + OFF_WO, wtlo + OFF_WO, bo, out, MQ_ALL == 0 ? DQ : INNER);
}

// round 10
// speedup vs baseline: 2.4007x; 1.2941x over previous
#include <cuda_runtime.h>
#include <cuda_bf16.h>
#include <math_constants.h>
#include <cstdint>

// ---------------------------------------------------------------------------
// CrossAttention: out = softmax((xWq)(ctxWk)^T * scale) (ctxWv) Wo + bo
// Round 9: R8 design with the V trans-ldmatrix addressing bug fixed
// (correct d-tile mapping; no reads into row padding).
// ---------------------------------------------------------------------------

#define B_     4
#define NQ     2048
#define NK     1024
#define DQ     512
#define DC     768
#define HEADS  8
#define DHEAD  64
#define INNER  512
#define MQ_ALL (B_*NQ)        // 8192
#define MK_ALL (B_*NK)        // 4096
#define SCALE_ 0.125f

// pre-split activations / intermediates (bf16 hi/lo pairs)
__device__ __nv_bfloat16 g_xh [MQ_ALL * DQ],    g_xl [MQ_ALL * DQ];
__device__ __nv_bfloat16 g_ch [MK_ALL * DC],    g_cl [MK_ALL * DC];
__device__ __nv_bfloat16 g_qh [MQ_ALL * INNER], g_ql [MQ_ALL * INNER];
__device__ __nv_bfloat16 g_kh [MK_ALL * INNER], g_kl [MK_ALL * INNER];
__device__ __nv_bfloat16 g_vh [MK_ALL * INNER], g_vl [MK_ALL * INNER];
__device__ __nv_bfloat16 g_aoh[MQ_ALL * INNER], g_aol[MQ_ALL * INNER];

// transposed+split weights [N][K]
#define OFF_WQ 0
#define OFF_WK (512*512)
#define OFF_WV (OFF_WK + 512*768)
#define OFF_WO (OFF_WV + 512*768)
#define WT_TOTAL (OFF_WO + 512*512)
__device__ __nv_bfloat16 g_wthi[WT_TOTAL];
__device__ __nv_bfloat16 g_wtlo[WT_TOTAL];

// ---------------------------------------------------------------------------
// helpers
// ---------------------------------------------------------------------------
__device__ __forceinline__ uint32_t smem_u32(const void* p) {
    uint32_t a;
    asm("{ .reg .u64 t; cvta.to.shared.u64 t, %1; cvt.u32.u64 %0, t; }"
        : "=r"(a) : "l"(p));
    return a;
}
__device__ __forceinline__ void cp16(uint32_t saddr, const void* g) {
    asm volatile("cp.async.cg.shared.global [%0], [%1], 16;"
                 :: "r"(saddr), "l"(g));
}
__device__ __forceinline__ void cp_commit() {
    asm volatile("cp.async.commit_group;" ::: "memory");
}
template <int N> __device__ __forceinline__ void cp_wait() {
    asm volatile("cp.async.wait_group %0;" :: "n"(N) : "memory");
}
__device__ __forceinline__ void ldsm_x4(uint32_t& r0, uint32_t& r1,
                                        uint32_t& r2, uint32_t& r3, uint32_t addr) {
    asm volatile("ldmatrix.sync.aligned.m8n8.x4.shared.b16 {%0,%1,%2,%3}, [%4];"
                 : "=r"(r0), "=r"(r1), "=r"(r2), "=r"(r3) : "r"(addr));
}
__device__ __forceinline__ void ldsm_x4_t(uint32_t& r0, uint32_t& r1,
                                          uint32_t& r2, uint32_t& r3, uint32_t addr) {
    asm volatile("ldmatrix.sync.aligned.m8n8.x4.trans.shared.b16 {%0,%1,%2,%3}, [%4];"
                 : "=r"(r0), "=r"(r1), "=r"(r2), "=r"(r3) : "r"(addr));
}
__device__ __forceinline__ void mma16816(float* c, const uint32_t* a,
                                         uint32_t b0, uint32_t b1) {
    asm volatile(
        "mma.sync.aligned.m16n8k16.row.col.f32.bf16.bf16.f32 "
        "{%0,%1,%2,%3}, {%4,%5,%6,%7}, {%8,%9}, {%0,%1,%2,%3};"
        : "+f"(c[0]), "+f"(c[1]), "+f"(c[2]), "+f"(c[3])
        : "r"(a[0]), "r"(a[1]), "r"(a[2]), "r"(a[3]), "r"(b0), "r"(b1));
}
__device__ __forceinline__ uint32_t packbf2(float a, float b) {
    __nv_bfloat162 t = __floats2bfloat162_rn(a, b);
    return *reinterpret_cast<uint32_t*>(&t);
}
__device__ __forceinline__ float bfhi(float x) {
    return __bfloat162float(__float2bfloat16(x));
}

// ---------------------------------------------------------------------------
// Weight transpose + split: W[K,N] fp32 -> hi/lo [N,K] bf16
// ---------------------------------------------------------------------------
__global__ void __launch_bounds__(256)
wsplit(const float* __restrict__ W, __nv_bfloat16* __restrict__ hi,
       __nv_bfloat16* __restrict__ lo, int K, int N)
{
    __shared__ float t[32][33];
    const int k0 = blockIdx.x * 32, n0 = blockIdx.y * 32;
    const int tx = threadIdx.x & 31, ty = threadIdx.x >> 5;
    #pragma unroll
    for (int i = 0; i < 32; i += 8)
        t[ty + i][tx] = W[(size_t)(k0 + ty + i) * N + n0 + tx];
    __syncthreads();
    #pragma unroll
    for (int i = 0; i < 32; i += 8) {
        float x = t[tx][ty + i];
        __nv_bfloat16 h = __float2bfloat16(x);
        __nv_bfloat16 l = __float2bfloat16(x - __bfloat162float(h));
        size_t o = (size_t)(n0 + ty + i) * K + k0 + tx;
        hi[o] = h; lo[o] = l;
    }
}

// ---------------------------------------------------------------------------
// Activation split: fp32 [n4*4] -> hi/lo bf16 (elementwise)
// ---------------------------------------------------------------------------
__global__ void __launch_bounds__(256)
asplit(const float* __restrict__ A, __nv_bfloat16* __restrict__ hi,
       __nv_bfloat16* __restrict__ lo, int n4)
{
    int i = blockIdx.x * 256 + threadIdx.x;
    if (i < n4) {
        float4 v = ((const float4*)A)[i];
        ((uint2*)hi)[i] = make_uint2(packbf2(v.x, v.y), packbf2(v.z, v.w));
        ((uint2*)lo)[i] = make_uint2(packbf2(v.x - bfhi(v.x), v.y - bfhi(v.y)),
                                     packbf2(v.z - bfhi(v.z), v.w - bfhi(v.w)));
    }
}

// ---------------------------------------------------------------------------
// GEMM (all-bf16 operands, split 3-MMA): C[M,512] = A[M,K] @ B^T[512,K]
// Output: fp32+bias (Cf) or split hi/lo with scale (Chi/Clo).
// CTA 128x128, BK=32, cp.async double buffer.
// ---------------------------------------------------------------------------
#define GS_AH 0
#define GS_AL 10240
#define GS_BH 20480
#define GS_BL 30720
#define GS_BUF 40960
#define GEMM_SMEM (2 * GS_BUF)

__global__ void __launch_bounds__(256, 1)
sgemm_b(const __nv_bfloat16* __restrict__ Ahi, const __nv_bfloat16* __restrict__ Alo,
        const __nv_bfloat16* __restrict__ Bhi, const __nv_bfloat16* __restrict__ Blo,
        const float* __restrict__ bias, float* __restrict__ Cf,
        __nv_bfloat16* __restrict__ Chi, __nv_bfloat16* __restrict__ Clo,
        float scale, int K)
{
    extern __shared__ char smem[];
    const uint32_t sb = smem_u32(smem);
    const int tid  = threadIdx.x;
    const int lane = tid & 31;
    const int wid  = tid >> 5;
    const int wm   = (wid & 1) * 64;
    const int wn   = (wid >> 1) * 32;
    const int m0   = blockIdx.y * 128;
    const int n0   = blockIdx.x * 128;

    float acc[4][4][4];
    #pragma unroll
    for (int mi = 0; mi < 4; ++mi)
        #pragma unroll
        for (int ni = 0; ni < 4; ++ni)
            #pragma unroll
            for (int r = 0; r < 4; ++r) acc[mi][ni][r] = 0.f;

    const int nch = K >> 5;
    const int lr = lane & 15;
    const int lc = (lane >> 4) << 3;

    #pragma unroll
    for (int i = 0; i < 2; ++i) {
        int idx = tid + i * 256;
        int row = idx >> 2, g = idx & 3;
        uint32_t so = (uint32_t)(row * 80 + g * 16);
        cp16(sb + GS_AH + so, Ahi + (size_t)(m0 + row) * K + g * 8);
        cp16(sb + GS_AL + so, Alo + (size_t)(m0 + row) * K + g * 8);
        cp16(sb + GS_BH + so, Bhi + (size_t)(n0 + row) * K + g * 8);
        cp16(sb + GS_BL + so, Blo + (size_t)(n0 + row) * K + g * 8);
    }
    cp_commit();

    for (int c = 0; c < nch; ++c) {
        const uint32_t bufo = (uint32_t)((c & 1) * GS_BUF);
        const bool more = (c + 1 < nch);
        if (more) {
            const int k0n = (c + 1) << 5;
            const uint32_t nb = (uint32_t)(((c + 1) & 1) * GS_BUF);
            #pragma unroll
            for (int i = 0; i < 2; ++i) {
                int idx = tid + i * 256;
                int row = idx >> 2, g = idx & 3;
                uint32_t so = (uint32_t)(row * 80 + g * 16);
                cp16(sb + nb + GS_AH + so, Ahi + (size_t)(m0 + row) * K + k0n + g * 8);
                cp16(sb + nb + GS_AL + so, Alo + (size_t)(m0 + row) * K + k0n + g * 8);
                cp16(sb + nb + GS_BH + so, Bhi + (size_t)(n0 + row) * K + k0n + g * 8);
                cp16(sb + nb + GS_BL + so, Blo + (size_t)(n0 + row) * K + k0n + g * 8);
            }
            cp_commit();
            cp_wait<1>();
        } else {
            cp_wait<0>();
        }
        __syncthreads();

        #pragma unroll
        for (int ks = 0; ks < 32; ks += 16) {
            uint32_t ah[4][4], al[4][4], bh[2][4], bl[2][4];
            #pragma unroll
            for (int mi = 0; mi < 4; ++mi) {
                uint32_t off = (uint32_t)((wm + mi * 16 + lr) * 80 + (ks + lc) * 2);
                ldsm_x4(ah[mi][0], ah[mi][1], ah[mi][2], ah[mi][3], sb + bufo + GS_AH + off);
                ldsm_x4(al[mi][0], al[mi][1], al[mi][2], al[mi][3], sb + bufo + GS_AL + off);
            }
            #pragma unroll
            for (int nt = 0; nt < 2; ++nt) {
                uint32_t off = (uint32_t)((wn + nt * 16 + lr) * 80 + (ks + lc) * 2);
                ldsm_x4(bh[nt][0], bh[nt][1], bh[nt][2], bh[nt][3], sb + bufo + GS_BH + off);
                ldsm_x4(bl[nt][0], bl[nt][1], bl[nt][2], bl[nt][3], sb + bufo + GS_BL + off);
            }
            #pragma unroll
            for (int mi = 0; mi < 4; ++mi)
                #pragma unroll
                for (int ni = 0; ni < 4; ++ni) {
                    int nt = ni >> 1, sel = ni & 1;
                    mma16816(acc[mi][ni], ah[mi], bh[nt][sel], bh[nt][sel + 2]);
                    mma16816(acc[mi][ni], ah[mi], bl[nt][sel], bl[nt][sel + 2]);
                    mma16816(acc[mi][ni], al[mi], bh[nt][sel], bh[nt][sel + 2]);
                }
        }
        __syncthreads();
    }

    const int qrow = lane >> 2;
    const int qcol = (lane & 3) * 2;
    #pragma unroll
    for (int mi = 0; mi < 4; ++mi) {
        #pragma unroll
        for (int ni = 0; ni < 4; ++ni) {
            int row0 = m0 + wm + mi * 16 + qrow;
            int col  = n0 + wn + ni * 8 + qcol;
            if (Cf) {
                float2 o0 = make_float2(acc[mi][ni][0], acc[mi][ni][1]);
                float2 o1 = make_float2(acc[mi][ni][2], acc[mi][ni][3]);
                float2 bb = *(const float2*)&bias[col];
                o0.x += bb.x; o0.y += bb.y;
                o1.x += bb.x; o1.y += bb.y;
                *(float2*)&Cf[(size_t)row0 * 512 + col]       = o0;
                *(float2*)&Cf[(size_t)(row0 + 8) * 512 + col] = o1;
            } else {
                float v0 = acc[mi][ni][0] * scale, v1 = acc[mi][ni][1] * scale;
                float v2 = acc[mi][ni][2] * scale, v3 = acc[mi][ni][3] * scale;
                *(uint32_t*)&Chi[(size_t)row0 * 512 + col] = packbf2(v0, v1);
                *(uint32_t*)&Clo[(size_t)row0 * 512 + col] =
                    packbf2(v0 - bfhi(v0), v1 - bfhi(v1));
                *(uint32_t*)&Chi[(size_t)(row0 + 8) * 512 + col] = packbf2(v2, v3);
                *(uint32_t*)&Clo[(size_t)(row0 + 8) * 512 + col] =
                    packbf2(v2 - bfhi(v2), v3 - bfhi(v3));
            }
        }
    }
}

// ---------------------------------------------------------------------------
// Flash attention, all-bf16-split inputs (Q pre-scaled), cp.async double
// buffer, ldmatrix.trans for V. CTA = (b,h) x 128 q-rows; 8 warps x 16 rows.
// smem/buffer: KH,KL,VH,VL each [128][72] bf16 (stride 144B).
// ---------------------------------------------------------------------------
#define AT_KH 0
#define AT_KL 18432
#define AT_VH 36864
#define AT_VL 55296
#define AT_BUF 73728
#define ATTN_SMEM (2 * AT_BUF)     // 147456

__global__ void __launch_bounds__(256, 1)
attn_mma(const __nv_bfloat16* __restrict__ qh_, const __nv_bfloat16* __restrict__ ql_,
         const __nv_bfloat16* __restrict__ kh_, const __nv_bfloat16* __restrict__ kl_,
         const __nv_bfloat16* __restrict__ vh_, const __nv_bfloat16* __restrict__ vl_,
         __nv_bfloat16* __restrict__ aoh, __nv_bfloat16* __restrict__ aol)
{
    extern __shared__ char smem[];
    const uint32_t sb = smem_u32(smem);
    const int tid  = threadIdx.x;
    const int lane = tid & 31;
    const int wid  = tid >> 5;
    const int wq   = wid * 16;
    const int lr   = lane & 15;
    const int lc   = (lane >> 4) << 3;

    const int bh = blockIdx.y;
    const int b  = bh >> 3;
    const int h  = bh & 7;
    const int qbase = b * NQ + blockIdx.x * 128;
    const int kbase = b * NK;
    const int hcol  = h * DHEAD;

    // ---- stage Q tile (pre-scaled, pre-split) into buf0 KH/KL area ----
    #pragma unroll
    for (int i = 0; i < 4; ++i) {
        int idx = tid + i * 256;
        int row = idx >> 3, g = idx & 7;
        size_t go = (size_t)(qbase + row) * INNER + hcol + g * 8;
        uint32_t so = (uint32_t)(row * 144 + g * 16);
        *(uint4*)(smem + AT_KH + so) = *(const uint4*)&qh_[go];
        *(uint4*)(smem + AT_KL + so) = *(const uint4*)&ql_[go];
    }
    __syncthreads();

    uint32_t qh[4][4], ql[4][4];
    #pragma unroll
    for (int ks = 0; ks < 4; ++ks) {
        uint32_t off = (uint32_t)((wq + lr) * 144 + (ks * 16 + lc) * 2);
        ldsm_x4(qh[ks][0], qh[ks][1], qh[ks][2], qh[ks][3], sb + AT_KH + off);
        ldsm_x4(ql[ks][0], ql[ks][1], ql[ks][2], ql[ks][3], sb + AT_KL + off);
    }
    __syncthreads();   // Q frags consumed before cp.async overwrites buf0

    // ---- prefetch KV tile 0 into buf0 ----
    {
        #pragma unroll
        for (int i = 0; i < 4; ++i) {
            int idx = tid + i * 256;
            int row = idx >> 3, g = idx & 7;
            size_t go = (size_t)(kbase + row) * INNER + hcol + g * 8;
            uint32_t so = (uint32_t)(row * 144 + g * 16);
            cp16(sb + AT_KH + so, kh_ + go);
            cp16(sb + AT_KL + so, kl_ + go);
            cp16(sb + AT_VH + so, vh_ + go);
            cp16(sb + AT_VL + so, vl_ + go);
        }
        cp_commit();
    }

    float mrow[2] = {-CUDART_INF_F, -CUDART_INF_F};
    float lrow[2] = {0.f, 0.f};
    float oacc[8][4];
    #pragma unroll
    for (int ni = 0; ni < 8; ++ni)
        #pragma unroll
        for (int r = 0; r < 4; ++r) oacc[ni][r] = 0.f;

    for (int jt = 0; jt < NK / 128; ++jt) {
        const uint32_t bufo = (uint32_t)((jt & 1) * AT_BUF);
        const bool more = (jt + 1 < NK / 128);
        if (more) {
            const int krn = kbase + (jt + 1) * 128;
            const uint32_t nb = (uint32_t)(((jt + 1) & 1) * AT_BUF);
            #pragma unroll
            for (int i = 0; i < 4; ++i) {
                int idx = tid + i * 256;
                int row = idx >> 3, g = idx & 7;
                size_t go = (size_t)(krn + row) * INNER + hcol + g * 8;
                uint32_t so = (uint32_t)(row * 144 + g * 16);
                cp16(sb + nb + AT_KH + so, kh_ + go);
                cp16(sb + nb + AT_KL + so, kl_ + go);
                cp16(sb + nb + AT_VH + so, vh_ + go);
                cp16(sb + nb + AT_VL + so, vl_ + go);
            }
            cp_commit();
            cp_wait<1>();
        } else {
            cp_wait<0>();
        }
        __syncthreads();

        // ---- S = Q K^T (3-MMA split) ----
        float sacc[16][4];
        #pragma unroll
        for (int ni = 0; ni < 16; ++ni)
            #pragma unroll
            for (int r = 0; r < 4; ++r) sacc[ni][r] = 0.f;

        #pragma unroll
        for (int ks = 0; ks < 4; ++ks) {
            #pragma unroll
            for (int nt = 0; nt < 8; ++nt) {
                uint32_t off = (uint32_t)((nt * 16 + lr) * 144 + (ks * 16 + lc) * 2);
                uint32_t kh0, kh1, kh2, kh3, kl0, kl1, kl2, kl3;
                ldsm_x4(kh0, kh1, kh2, kh3, sb + bufo + AT_KH + off);
                ldsm_x4(kl0, kl1, kl2, kl3, sb + bufo + AT_KL + off);
                uint32_t khr[4] = {kh0, kh1, kh2, kh3};
                uint32_t klr[4] = {kl0, kl1, kl2, kl3};
                #pragma unroll
                for (int sel = 0; sel < 2; ++sel) {
                    int ni = nt * 2 + sel;
                    mma16816(sacc[ni], qh[ks], khr[sel], khr[sel + 2]);
                    mma16816(sacc[ni], qh[ks], klr[sel], klr[sel + 2]);
                    mma16816(sacc[ni], ql[ks], khr[sel], khr[sel + 2]);
                }
            }
        }

        // ---- online softmax ----
        #pragma unroll
        for (int half = 0; half < 2; ++half) {
            const int c0 = half * 2, c1 = half * 2 + 1;
            float rmax = -CUDART_INF_F;
            #pragma unroll
            for (int ni = 0; ni < 16; ++ni)
                rmax = fmaxf(rmax, fmaxf(sacc[ni][c0], sacc[ni][c1]));
            rmax = fmaxf(rmax, __shfl_xor_sync(0xffffffffu, rmax, 1));
            rmax = fmaxf(rmax, __shfl_xor_sync(0xffffffffu, rmax, 2));
            float nm    = fmaxf(mrow[half], rmax);
            float alpha = __expf(mrow[half] - nm);
            mrow[half] = nm;

            float rsum = 0.f;
            #pragma unroll
            for (int ni = 0; ni < 16; ++ni) {
                sacc[ni][c0] = __expf(sacc[ni][c0] - nm);
                sacc[ni][c1] = __expf(sacc[ni][c1] - nm);
                rsum += sacc[ni][c0] + sacc[ni][c1];
            }
            rsum += __shfl_xor_sync(0xffffffffu, rsum, 1);
            rsum += __shfl_xor_sync(0xffffffffu, rsum, 2);

            lrow[half] = lrow[half] * alpha + rsum;
            #pragma unroll
            for (int ni = 0; ni < 8; ++ni) {
                oacc[ni][c0] *= alpha;
                oacc[ni][c1] *= alpha;
            }
        }

        // ---- O += P V (P split in regs; V via ldmatrix.trans from [j][d]) ----
        // Correct mapping: one x4.trans at rows j0+lr, col d0+lc (d0 = vt*16)
        // yields (m0,m1) = b-frag for n-tile d0, (m2,m3) = b-frag for d0+8.
        #pragma unroll
        for (int ks2 = 0; ks2 < 8; ++ks2) {
            const int e = ks2 * 2, od = ks2 * 2 + 1;
            float p00 = sacc[e][0],  p01 = sacc[e][1],  p10 = sacc[e][2],  p11 = sacc[e][3];
            float r00 = sacc[od][0], r01 = sacc[od][1], r10 = sacc[od][2], r11 = sacc[od][3];
            uint32_t ph[4] = {packbf2(p00, p01), packbf2(p10, p11),
                              packbf2(r00, r01), packbf2(r10, r11)};
            uint32_t pl[4] = {packbf2(p00 - bfhi(p00), p01 - bfhi(p01)),
                              packbf2(p10 - bfhi(p10), p11 - bfhi(p11)),
                              packbf2(r00 - bfhi(r00), r01 - bfhi(r01)),
                              packbf2(r10 - bfhi(r10), r11 - bfhi(r11))};
            #pragma unroll
            for (int vt = 0; vt < 4; ++vt) {
                uint32_t off = (uint32_t)((ks2 * 16 + lr) * 144 + (vt * 16 + lc) * 2);
                uint32_t vh0, vh1, vh2, vh3, vl0, vl1, vl2, vl3;
                ldsm_x4_t(vh0, vh1, vh2, vh3, sb + bufo + AT_VH + off);
                ldsm_x4_t(vl0, vl1, vl2, vl3, sb + bufo + AT_VL + off);
                mma16816(oacc[vt * 2 + 0], ph, vh0, vh1);
                mma16816(oacc[vt * 2 + 0], pl, vh0, vh1);
                mma16816(oacc[vt * 2 + 0], ph, vl0, vl1);
                mma16816(oacc[vt * 2 + 1], ph, vh2, vh3);
                mma16816(oacc[vt * 2 + 1], pl, vh2, vh3);
                mma16816(oacc[vt * 2 + 1], ph, vl2, vl3);
            }
        }
        __syncthreads();
    }

    // ---- normalize + write split bf16 (head-merged) ----
    const float inv0 = 1.0f / lrow[0];
    const float inv1 = 1.0f / lrow[1];
    const int row0 = qbase + wq + (lane >> 2);
    #pragma unroll
    for (int ni = 0; ni < 8; ++ni) {
        int col = hcol + ni * 8 + (lane & 3) * 2;
        float v0 = oacc[ni][0] * inv0, v1 = oacc[ni][1] * inv0;
        float v2 = oacc[ni][2] * inv1, v3 = oacc[ni][3] * inv1;
        *(uint32_t*)&aoh[(size_t)row0 * INNER + col] = packbf2(v0, v1);
        *(uint32_t*)&aol[(size_t)row0 * INNER + col] =
            packbf2(v0 - bfhi(v0), v1 - bfhi(v1));
        *(uint32_t*)&aoh[(size_t)(row0 + 8) * INNER + col] = packbf2(v2, v3);
        *(uint32_t*)&aol[(size_t)(row0 + 8) * INNER + col] =
            packbf2(v2 - bfhi(v2), v3 - bfhi(v3));
    }
}

// ---------------------------------------------------------------------------
// Launch
// ---------------------------------------------------------------------------
extern "C" void kernel_launch(void* const* d_in, const int* in_sizes, int n_in,
                              void* d_out, int out_size)
{
    (void)in_sizes; (void)n_in; (void)out_size;
    const float* x   = (const float*)d_in[0];
    const float* ctx = (const float*)d_in[1];
    const float* Wq  = (const float*)d_in[2];
    const float* Wk  = (const float*)d_in[3];
    const float* Wv  = (const float*)d_in[4];
    const float* Wo  = (const float*)d_in[5];
    const float* bo  = (const float*)d_in[6];
    float* out = (float*)d_out;

    __nv_bfloat16 *xh, *xl, *ch, *cl, *qh, *ql, *kh, *kl, *vh, *vl, *aoh, *aol;
    __nv_bfloat16 *wthi, *wtlo;
    cudaGetSymbolAddress((void**)&xh,  g_xh);  cudaGetSymbolAddress((void**)&xl,  g_xl);
    cudaGetSymbolAddress((void**)&ch,  g_ch);  cudaGetSymbolAddress((void**)&cl,  g_cl);
    cudaGetSymbolAddress((void**)&qh,  g_qh);  cudaGetSymbolAddress((void**)&ql,  g_ql);
    cudaGetSymbolAddress((void**)&kh,  g_kh);  cudaGetSymbolAddress((void**)&kl,  g_kl);
    cudaGetSymbolAddress((void**)&vh,  g_vh);  cudaGetSymbolAddress((void**)&vl,  g_vl);
    cudaGetSymbolAddress((void**)&aoh, g_aoh); cudaGetSymbolAddress((void**)&aol, g_aol);
    cudaGetSymbolAddress((void**)&wthi, g_wthi);
    cudaGetSymbolAddress((void**)&wtlo, g_wtlo);

    (void)cudaFuncSetAttribute(attn_mma,
                               cudaFuncAttributeMaxDynamicSharedMemorySize, ATTN_SMEM);
    (void)cudaFuncSetAttribute(sgemm_b,
                               cudaFuncAttributeMaxDynamicSharedMemorySize, GEMM_SMEM);

    // weight transpose + split
    wsplit<<<dim3(DQ/32,    INNER/32), 256>>>(Wq, wthi + OFF_WQ, wtlo + OFF_WQ, DQ,    INNER);
    wsplit<<<dim3(DC/32,    INNER/32), 256>>>(Wk, wthi + OFF_WK, wtlo + OFF_WK, DC,    INNER);
    wsplit<<<dim3(DC/32,    INNER/32), 256>>>(Wv, wthi + OFF_WV, wtlo + OFF_WV, DC,    INNER);
    wsplit<<<dim3(INNER/32, DQ/32),    256>>>(Wo, wthi + OFF_WO, wtlo + OFF_WO, INNER, DQ);

    // activation split
    asplit<<<(MQ_ALL*DQ/4 + 255)/256, 256>>>(x,   xh, xl, MQ_ALL*DQ/4);
    asplit<<<(MK_ALL*DC/4 + 255)/256, 256>>>(ctx, ch, cl, MK_ALL*DC/4);

    // projections (split bf16 outputs; Q pre-scaled)
    sgemm_b<<<dim3(4, MQ_ALL/128), 256, GEMM_SMEM>>>(xh, xl, wthi + OFF_WQ, wtlo + OFF_WQ,
                                                     nullptr, nullptr, qh, ql, SCALE_, DQ);
    sgemm_b<<<dim3(4, MK_ALL/128), 256, GEMM_SMEM>>>(ch, cl, wthi + OFF_WK, wtlo + OFF_WK,
                                                     nullptr, nullptr, kh, kl, 1.0f, DC);
    sgemm_b<<<dim3(4, MK_ALL/128), 256, GEMM_SMEM>>>(ch, cl, wthi + OFF_WV, wtlo + OFF_WV,
                                                     nullptr, nullptr, vh, vl, 1.0f, DC);

    // attention
    attn_mma<<<dim3(NQ / 128, B_ * HEADS), 256, ATTN_SMEM>>>(qh, ql, kh, kl, vh, vl, aoh, aol);

    // output projection + bias -> d_out (fp32)
    sgemm_b<<<dim3(4, MQ_ALL/128), 256, GEMM_SMEM>>>(aoh, aol, wthi + OFF_WO, wtlo + OFF_WO,
                                                     bo, out, nullptr, nullptr, 1.0f, INNER);
}